// round 11
// baseline (speedup 1.0000x reference)
#include <cuda_runtime.h>
#include <cuda_fp16.h>
#include <mma.h>
#include <math.h>

using namespace nvcuda;

#define N_NODES 100000
#define N_EDGES 1600000
#define F_IN    128
#define F_E     32
#define DH      128   // D*H
#define NH      4     // heads
#define FULLM   0xffffffffu
#define SCAN_BLOCKS 98          // ceil(100000/1024)
#define HIST_BLOCKS 6250        // 6250*256 = 1.6M edges
#define GEMM_TILES  1563        // ceil(100000/64)
#define AGG_NPB     64          // nodes per block in agg_out
#define AGG_BLOCKS  1563        // ceil(100000/64)

// -------- scratch (static device globals; zero-initialized at load) --------
__device__ __half2 g_np_h[(size_t)N_NODES * 64];      // node_proj fp16, 25.6 MB
__device__ float g_ssrc[N_NODES * NH];
__device__ float g_v[NH * F_E];                       // W_edge @ a_edge (per head)
__device__ __half g_Wo_h[DH * 32];                    // W_out in fp16
__device__ int g_cnt[N_NODES];                        // zeroed by prev run's agg_out
__device__ int g_rowptr[N_NODES + 1];
__device__ int g_head[N_NODES];
__device__ unsigned long long g_state[SCAN_BLOCKS];   // zeroed by prev run's agg_out
__device__ float4 g_p4[N_EDGES];                      // attn numerators, dst-sorted
__device__ int    g_src[N_EDGES];                     // src ids, dst-sorted

static __device__ __forceinline__ unsigned sm32(const void* p) {
    return (unsigned)__cvta_generic_to_shared(p);
}

// ===== launch 0: folds — v = We@a_edge, W_out -> fp16 =====
__global__ void __launch_bounds__(256) k_fold(const float* __restrict__ We,
                                              const float* __restrict__ AK,
                                              const float* __restrict__ Wo) {
    int t = threadIdx.x;
    if (t < 128) {
        int h = t >> 5, k = t & 31;
        float s = 0.f;
#pragma unroll
        for (int d = 0; d < 32; d++)
            s += We[k * DH + h * 32 + d] * AK[h * 96 + 64 + d];
        g_v[t] = s;
    }
#pragma unroll
    for (int i = 0; i < 16; i++) {
        int idx = i * 256 + t;
        g_Wo_h[idx] = __float2half_rn(Wo[idx]);
    }
}

// ===== launch 1: dst histogram =====
__global__ void __launch_bounds__(256) k_hist(const int* __restrict__ EI) {
    int e = blockIdx.x * 256 + threadIdx.x;
    int2 ei = reinterpret_cast<const int2*>(EI)[e];
    atomicAdd(&g_cnt[ei.y], 1);
}

// ===== launch 2: single-pass decoupled-lookback scan -> rowptr + head =====
__global__ void __launch_bounds__(1024) k_scan() {
    __shared__ int s[1024];
    __shared__ int sprefix;
    int t = threadIdx.x, b = blockIdx.x;
    int i = b * 1024 + t;
    int v = (i < N_NODES) ? g_cnt[i] : 0;
    s[t] = v;
    __syncthreads();
    for (int o = 1; o < 1024; o <<= 1) {
        int u = (t >= o) ? s[t - o] : 0;
        __syncthreads();
        s[t] += u;
        __syncthreads();
    }
    int excl = s[t] - v;
    int total = s[1023];

    if (t == 0) {
        unsigned long long st = ((b == 0 ? 2ull : 1ull) << 32) | (unsigned)total;
        atomicExch(&g_state[b], st);
        if (b == 0) sprefix = 0;
    }
    if (b > 0 && t < 32) {
        int lane = t;
        unsigned running = 0;
        int idx = b - 1;
        while (true) {
            int pi = idx - lane;
            unsigned long long sv_ = (pi >= 0) ? atomicAdd(&g_state[pi], 0ull)
                                               : (2ull << 32);
            int flag = (int)(sv_ >> 32);
            unsigned val = (unsigned)sv_;
            unsigned m2 = __ballot_sync(FULLM, flag == 2);
            unsigned m0 = __ballot_sync(FULLM, flag == 0);
            int f2 = m2 ? (__ffs(m2) - 1) : 32;
            int f0 = m0 ? (__ffs(m0) - 1) : 32;
            if (f2 < f0) {
                unsigned cc = (lane <= f2) ? val : 0;
#pragma unroll
                for (int o = 16; o >= 1; o >>= 1) cc += __shfl_down_sync(FULLM, cc, o);
                if (lane == 0) running += cc;
                break;
            } else if (f0 < 32) {
                unsigned cc = (lane < f0) ? val : 0;
#pragma unroll
                for (int o = 16; o >= 1; o >>= 1) cc += __shfl_down_sync(FULLM, cc, o);
                if (lane == 0) running += cc;
                idx -= f0;
            } else {
                unsigned cc = val;
#pragma unroll
                for (int o = 16; o >= 1; o >>= 1) cc += __shfl_down_sync(FULLM, cc, o);
                if (lane == 0) running += cc;
                idx -= 32;
            }
        }
        if (lane == 0) {
            atomicExch(&g_state[b], (2ull << 32) | (unsigned)(running + total));
            sprefix = (int)running;
        }
    }
    __syncthreads();
    int P = sprefix;
    if (i < N_NODES) {
        int r = excl + P;
        g_rowptr[i] = r;
        g_head[i] = r;
    }
    if (b == 0 && t == 0) g_rowptr[N_NODES] = N_EDGES;
}

// ===== launch 3 (PROFILED): node GEMM (wmma) + fused ssrc epilogue =====
__global__ void __launch_bounds__(256) k_gemm(const float* __restrict__ NF,
                                              const float* __restrict__ Wn,
                                              const float* __restrict__ AK) {
    __shared__ __align__(16) unsigned char sraw[49152];
    int t = threadIdx.x;
    int row0 = blockIdx.x * 64;
    __half* sW = reinterpret_cast<__half*>(sraw);            // 128x128 = 32 KB
    __half* sA = reinterpret_cast<__half*>(sraw + 32768);    // 64x128  = 16 KB
    float*  sC = reinterpret_cast<float*>(sraw + 32768);     // 64x64 f32 reuse

#pragma unroll
    for (int i = 0; i < 32; i++) {
        int idx = i * 256 + t;
        float2 w2 = reinterpret_cast<const float2*>(Wn)[idx];
        reinterpret_cast<__half2*>(sW)[idx] = __floats2half2_rn(w2.x, w2.y);
    }
#pragma unroll
    for (int i = 0; i < 8; i++) {
        int idx = i * 256 + t;
        int r = idx >> 5, c4 = idx & 31;
        int gr = row0 + r;
        float4 v = (gr < N_NODES)
            ? reinterpret_cast<const float4*>(NF)[(size_t)gr * 32 + c4]
            : make_float4(0.f, 0.f, 0.f, 0.f);
        __half2 h01 = __floats2half2_rn(v.x, v.y);
        __half2 h23 = __floats2half2_rn(v.z, v.w);
        uint2 raw;
        raw.x = *reinterpret_cast<unsigned*>(&h01);
        raw.y = *reinterpret_cast<unsigned*>(&h23);
        reinterpret_cast<uint2*>(sA)[idx] = raw;
    }
    __syncthreads();

    int w = t >> 5, wm = w >> 1, wn = w & 1;
    wmma::fragment<wmma::accumulator, 16, 16, 16, float> c[4];
#pragma unroll
    for (int j = 0; j < 4; j++) wmma::fill_fragment(c[j], 0.f);
#pragma unroll
    for (int k = 0; k < 8; k++) {
        wmma::fragment<wmma::matrix_a, 16, 16, 16, __half, wmma::row_major> a;
        wmma::load_matrix_sync(a, sA + (wm * 16) * 128 + k * 16, 128);
#pragma unroll
        for (int j = 0; j < 4; j++) {
            wmma::fragment<wmma::matrix_b, 16, 16, 16, __half, wmma::row_major> bf;
            wmma::load_matrix_sync(bf, sW + (k * 16) * 128 + wn * 64 + j * 16, 128);
            wmma::mma_sync(c[j], a, bf, c[j]);
        }
    }

#pragma unroll
    for (int jh = 0; jh < 2; jh++) {
        __syncthreads();
        if (wn == jh) {
#pragma unroll
            for (int j = 0; j < 4; j++)
                wmma::store_matrix_sync(sC + (wm * 16) * 64 + j * 16, c[j],
                                        64, wmma::mem_row_major);
        }
        __syncthreads();
#pragma unroll
        for (int i = 0; i < 8; i++) {
            int idx = i * 256 + t;
            int r = idx >> 5, c2 = idx & 31;
            int gr = row0 + r;
            if (gr < N_NODES) {
                float2 v = reinterpret_cast<const float2*>(sC)[r * 32 + c2];
                g_np_h[(size_t)gr * 64 + jh * 32 + c2] = __floats2half2_rn(v.x, v.y);
            }
        }
        if (t < 128) {
            int r = t >> 1, hh = t & 1, h = jh * 2 + hh;
            int gr = row0 + r;
            if (gr < N_NODES) {
                const float4* akp = reinterpret_cast<const float4*>(AK + h * 96);
                const float4* cr = reinterpret_cast<const float4*>(sC + r * 64 + hh * 32);
                float s = 0.f;
#pragma unroll
                for (int k4 = 0; k4 < 8; k4++) {
                    float4 a = cr[k4];
                    float4 ak = akp[k4];
                    s += a.x * ak.x + a.y * ak.y + a.z * ak.z + a.w * ak.w;
                }
                g_ssrc[gr * 4 + h] = s;
            }
        }
    }
}

// ===== launch 4: permute via wmma edge-score GEMM =====
// 256 edges/block: s_edge(256x4) = EF_h(256x32) @ V(32x16, 4 cols used)
__global__ void __launch_bounds__(256) k_permute(const int* __restrict__ EI,
                                                 const float* __restrict__ EF) {
    __shared__ __align__(16) unsigned char psm[21504];
    __half* sEFh = reinterpret_cast<__half*>(psm);        // 256x32 fp16 (16 KB)
    float*  sC   = reinterpret_cast<float*>(psm);         // 256x20 f32 (alias)
    __half* sV   = reinterpret_cast<__half*>(psm + 20480);// 32x16 fp16 (1 KB)
    int t = threadIdx.x, w = t >> 5;
    int e0 = blockIdx.x * 256;

    // early: edge endpoints + random ssrc gather (in flight during staging)
    int2 ei = reinterpret_cast<const int2*>(EI)[e0 + t];
    float4 ss4 = *reinterpret_cast<const float4*>(&g_ssrc[ei.x * 4]);

#pragma unroll
    for (int i = 0; i < 2; i++) {
        int idx = i * 256 + t;
        int k = idx >> 4, cn = idx & 15;
        sV[idx] = (cn < 4) ? __float2half_rn(g_v[cn * 32 + k]) : __ushort_as_half(0);
    }
#pragma unroll
    for (int i = 0; i < 8; i++) {
        int idx = i * 256 + t;
        int el = idx >> 3, c4 = idx & 7;
        float4 v = reinterpret_cast<const float4*>(EF)[(size_t)(e0 + el) * 8 + c4];
        __half2 ha = __floats2half2_rn(v.x, v.y);
        __half2 hb = __floats2half2_rn(v.z, v.w);
        uint2 raw;
        raw.x = *reinterpret_cast<unsigned*>(&ha);
        raw.y = *reinterpret_cast<unsigned*>(&hb);
        *reinterpret_cast<uint2*>(&sEFh[el * 32 + c4 * 4]) = raw;
    }
    __syncthreads();

    wmma::fragment<wmma::accumulator, 16, 16, 16, float> cf[2];
#pragma unroll
    for (int mi = 0; mi < 2; mi++) {
        int mt = 2 * w + mi;
        wmma::fill_fragment(cf[mi], 0.f);
#pragma unroll
        for (int kk = 0; kk < 2; kk++) {
            wmma::fragment<wmma::matrix_a, 16, 16, 16, __half, wmma::row_major> a;
            wmma::load_matrix_sync(a, sEFh + (mt * 16) * 32 + kk * 16, 32);
            wmma::fragment<wmma::matrix_b, 16, 16, 16, __half, wmma::row_major> bf;
            wmma::load_matrix_sync(bf, sV + (kk * 16) * 16, 16);
            wmma::mma_sync(cf[mi], a, bf, cf[mi]);
        }
    }
    __syncthreads();   // A fully consumed before aliasing writes
#pragma unroll
    for (int mi = 0; mi < 2; mi++)
        wmma::store_matrix_sync(sC + (2 * w + mi) * 16 * 20, cf[mi], 20,
                                wmma::mem_row_major);
    __syncthreads();

    float4 se = *reinterpret_cast<const float4*>(&sC[t * 20]);
    float4 p;
    p.x = __expf(ss4.x + se.x);
    p.y = __expf(ss4.y + se.y);
    p.z = __expf(ss4.z + se.z);
    p.w = __expf(ss4.w + se.w);
    int pos = atomicAdd(&g_head[ei.y], 1);
    g_p4[pos] = p;
    g_src[pos] = ei.x;
}

// ===== launch 5: gather-aggregate (16-lane pairs) + wmma out-GEMM + gelu ===
// block = 64 nodes; warp = 8 contiguous nodes; edges 16-lane rows (pairs).
__global__ void __launch_bounds__(256) k_agg_out(const float* __restrict__ bo,
                                                 float* __restrict__ out) {
    __shared__ __align__(16) unsigned char sm[27008];
    float*  s_p   = reinterpret_cast<float*>(sm);            // [2][8][32*4] 8 KB
    int*    s_srb = reinterpret_cast<int*>(sm + 8192);       // [2][8][32]   2 KB
    __half* s_Ah  = reinterpret_cast<__half*>(sm + 10240);   // [64][128]   16 KB
    float*  sD    = reinterpret_cast<float*>(sm);            // alias (epilogue)
    float*  sb    = reinterpret_cast<float*>(sm + 26624);    // 32 floats
    int t = threadIdx.x, lane = t & 31, w = t >> 5;

    // re-zero hist/scan state for the NEXT run
    {
        int zi = blockIdx.x * 256 + t;
        if (zi < N_NODES) g_cnt[zi] = 0;
        if (blockIdx.x == 0 && t < SCAN_BLOCKS) g_state[t] = 0ull;
    }
    if (t < 32) sb[t] = bo[t];

    int n0 = blockIdx.x * AGG_NPB;
    int nw0 = n0 + w * 8;
    int nw1 = min(nw0 + 8, N_NODES);

    if (nw0 < N_NODES) {
        int ebeg = g_rowptr[nw0];
        int eend = g_rowptr[nw1];
        int half = lane >> 4, li = lane & 15, h = li >> 2;
        const uint4* np4 = reinterpret_cast<const uint4*>(g_np_h);

        auto issue = [&](int cs) {
            int buf = ((cs - ebeg) >> 5) & 1;
            int j = cs + lane;
            if (j < eend) {
                unsigned ap = sm32(s_p + (buf * 8 + w) * 128 + lane * 4);
                asm volatile("cp.async.ca.shared.global [%0], [%1], 16;"
                             :: "r"(ap), "l"(g_p4 + j));
                unsigned as = sm32(s_srb + (buf * 8 + w) * 32 + lane);
                asm volatile("cp.async.ca.shared.global [%0], [%1], 4;"
                             :: "r"(as), "l"(g_src + j));
            }
            asm volatile("cp.async.commit_group;" ::: "memory");
        };

        if (ebeg < eend) {
            issue(ebeg);
            if (ebeg + 32 < eend) issue(ebeg + 32);
        }

        int j = ebeg;
        for (int n = nw0; n < nw1; n++) {
            int en = g_rowptr[n + 1];
            float acc[8] = {0.f, 0.f, 0.f, 0.f, 0.f, 0.f, 0.f, 0.f};
            float ds = 0.f;

            while (j < en) {
                int cb = ebeg + ((j - ebeg) & ~31);
                int ce = min(cb + 32, eend);
                if (j == cb) {
                    if (cb + 32 < eend) {
                        asm volatile("cp.async.wait_group 1;" ::: "memory");
                    } else {
                        asm volatile("cp.async.wait_group 0;" ::: "memory");
                    }
                    __syncwarp();
                }
                int buf = ((cb - ebeg) >> 5) & 1;
                const float* wp = s_p + (buf * 8 + w) * 128;
                const int* ws = s_srb + (buf * 8 + w) * 32;
                int stop = min(en, ce);
                int npair = (stop - j + 1) >> 1;
#pragma unroll 2
                for (int qp = 0; qp < npair; qp++) {
                    int e = j + qp * 2 + half;
                    bool valid = e < stop;
                    int qq = (e - ebeg) & 31;
                    int src = valid ? ws[qq] : 0;
                    float ph = valid ? wp[qq * 4 + h] : 0.f;
                    uint4 raw = np4[(size_t)src * 16 + li];
                    float2 f0 = __half22float2(*reinterpret_cast<__half2*>(&raw.x));
                    float2 f1 = __half22float2(*reinterpret_cast<__half2*>(&raw.y));
                    float2 f2 = __half22float2(*reinterpret_cast<__half2*>(&raw.z));
                    float2 f3 = __half22float2(*reinterpret_cast<__half2*>(&raw.w));
                    acc[0] += ph * f0.x; acc[1] += ph * f0.y;
                    acc[2] += ph * f1.x; acc[3] += ph * f1.y;
                    acc[4] += ph * f2.x; acc[5] += ph * f2.y;
                    acc[6] += ph * f3.x; acc[7] += ph * f3.y;
                    ds += ph;
                }
                j = stop;
                if (stop == ce) {
                    __syncwarp();
                    if (cb + 64 < eend) issue(cb + 64);
                }
            }

#pragma unroll
            for (int k = 0; k < 8; k++)
                acc[k] += __shfl_xor_sync(FULLM, acc[k], 16);
            ds += __shfl_xor_sync(FULLM, ds, 16);
            float inv = 1.f / (ds + 1e-8f);
            if (half == 0) {
                __half2 p0 = __floats2half2_rn(acc[0] * inv, acc[1] * inv);
                __half2 p1 = __floats2half2_rn(acc[2] * inv, acc[3] * inv);
                __half2 p2 = __floats2half2_rn(acc[4] * inv, acc[5] * inv);
                __half2 p3 = __floats2half2_rn(acc[6] * inv, acc[7] * inv);
                uint4 pk;
                pk.x = *reinterpret_cast<unsigned*>(&p0);
                pk.y = *reinterpret_cast<unsigned*>(&p1);
                pk.z = *reinterpret_cast<unsigned*>(&p2);
                pk.w = *reinterpret_cast<unsigned*>(&p3);
                *reinterpret_cast<uint4*>(&s_Ah[(n - n0) * 128 + li * 8]) = pk;
            }
        }
    }
    __syncthreads();

    // wmma epilogue: D(64x32) = A(64x128,fp16) @ Wo(128x32,fp16), fp32 acc
    {
        int mt = w & 3, nt = w >> 2;
        wmma::fragment<wmma::accumulator, 16, 16, 16, float> c;
        wmma::fill_fragment(c, 0.f);
#pragma unroll
        for (int kk = 0; kk < 8; kk++) {
            wmma::fragment<wmma::matrix_a, 16, 16, 16, __half, wmma::row_major> a;
            wmma::load_matrix_sync(a, s_Ah + (mt * 16) * 128 + kk * 16, 128);
            wmma::fragment<wmma::matrix_b, 16, 16, 16, __half, wmma::row_major> bf;
            wmma::load_matrix_sync(bf, g_Wo_h + (kk * 16) * 32 + nt * 16, 32);
            wmma::mma_sync(c, a, bf, c);
        }
        __syncthreads();
        wmma::store_matrix_sync(sD + (mt * 16) * 32 + nt * 16, c, 32,
                                wmma::mem_row_major);
    }
    __syncthreads();

    // gelu + coalesced store (512 float4)
#pragma unroll
    for (int i = 0; i < 2; i++) {
        int idx = i * 256 + t;
        int r = idx >> 3, c4 = idx & 7;
        int gn = n0 + r;
        if (gn < N_NODES) {
            float4 v = *reinterpret_cast<const float4*>(&sD[r * 32 + c4 * 4]);
            float4 bb = *reinterpret_cast<const float4*>(&sb[c4 * 4]);
            v.x += bb.x; v.y += bb.y; v.z += bb.z; v.w += bb.w;
            v.x = 0.5f * v.x * (1.f + erff(v.x * 0.70710678118f));
            v.y = 0.5f * v.y * (1.f + erff(v.y * 0.70710678118f));
            v.z = 0.5f * v.z * (1.f + erff(v.z * 0.70710678118f));
            v.w = 0.5f * v.w * (1.f + erff(v.w * 0.70710678118f));
            *reinterpret_cast<float4*>(&out[(size_t)gn * 32 + c4 * 4]) = v;
        }
    }
}

extern "C" void kernel_launch(void* const* d_in, const int* in_sizes, int n_in,
                              void* d_out, int out_size) {
    const float* NF = (const float*)d_in[0];   // node_features (N,128)
    const int*   EI = (const int*)  d_in[1];   // edge_index (E,2)
    const float* EF = (const float*)d_in[2];   // edge_features (E,32)
    const float* Wn = (const float*)d_in[3];   // W_node (128,128)
    const float* We = (const float*)d_in[4];   // W_edge (32,128)
    const float* AK = (const float*)d_in[5];   // attn_kernel (4,96)
    const float* Wo = (const float*)d_in[6];   // W_out (128,32)
    const float* bo = (const float*)d_in[7];   // b_out (32,)
    float* out = (float*)d_out;                // (N,32)

    k_fold<<<1, 256>>>(We, AK, Wo);
    k_hist<<<HIST_BLOCKS, 256>>>(EI);
    k_scan<<<SCAN_BLOCKS, 1024>>>();
    k_gemm<<<GEMM_TILES, 256>>>(NF, Wn, AK);     // profiled slot (index 3)
    k_permute<<<N_EDGES / 256, 256>>>(EI, EF);
    k_agg_out<<<AGG_BLOCKS, 256>>>(bo, out);
}

// round 12
// speedup vs baseline: 1.0364x; 1.0364x over previous
#include <cuda_runtime.h>
#include <cuda_fp16.h>
#include <mma.h>
#include <math.h>

using namespace nvcuda;

#define N_NODES 100000
#define N_EDGES 1600000
#define F_IN    128
#define F_E     32
#define DH      128   // D*H
#define NH      4     // heads
#define FULLM   0xffffffffu
#define SCAN_BLOCKS 98          // ceil(100000/1024)
#define HIST_BLOCKS 6250        // 6250*256 = 1.6M edges
#define GEMM_TILES  1563        // ceil(100000/64)
#define AGG_NPB     64          // nodes per block in agg_out
#define AGG_BLOCKS  1563        // ceil(100000/64)
#define SA_LD       136         // padded stride (halves) for A tile

// -------- scratch (static device globals; zero-initialized at load) --------
__device__ __half2 g_np_h[(size_t)N_NODES * 64];      // node_proj fp16, 25.6 MB
__device__ float g_ssrc[N_NODES * NH];
__device__ float g_v[NH * F_E];                       // W_edge @ a_edge (per head)
__device__ __half g_Wo_h[DH * 32];                    // W_out in fp16
__device__ __half g_Wn_h[F_IN * DH];                  // W_node in fp16 (32 KB)
__device__ int g_cnt[N_NODES];                        // zeroed by prev run's agg_out
__device__ int g_rowptr[N_NODES + 1];
__device__ int g_head[N_NODES];
__device__ unsigned long long g_state[SCAN_BLOCKS];   // zeroed by prev run's agg_out
__device__ float4 g_p4[N_EDGES];                      // attn numerators, dst-sorted
__device__ int    g_src[N_EDGES];                     // src ids, dst-sorted

static __device__ __forceinline__ unsigned sm32(const void* p) {
    return (unsigned)__cvta_generic_to_shared(p);
}

// ===== launch 0: folds — v = We@a_edge, W_out -> fp16, W_node -> fp16 =====
__global__ void __launch_bounds__(256) k_fold(const float* __restrict__ We,
                                              const float* __restrict__ AK,
                                              const float* __restrict__ Wo,
                                              const float* __restrict__ Wn) {
    int t = threadIdx.x;
    if (t < 128) {
        int h = t >> 5, k = t & 31;
        float s = 0.f;
#pragma unroll
        for (int d = 0; d < 32; d++)
            s += We[k * DH + h * 32 + d] * AK[h * 96 + 64 + d];
        g_v[t] = s;
    }
#pragma unroll
    for (int i = 0; i < 16; i++) {
        int idx = i * 256 + t;
        g_Wo_h[idx] = __float2half_rn(Wo[idx]);
    }
#pragma unroll
    for (int i = 0; i < 32; i++) {              // 8192 half2
        int idx = i * 256 + t;
        float2 w2 = reinterpret_cast<const float2*>(Wn)[idx];
        reinterpret_cast<__half2*>(g_Wn_h)[idx] = __floats2half2_rn(w2.x, w2.y);
    }
}

// ===== launch 1: hist + node GEMM (wmma, B from global fp16 W) =====
__global__ void __launch_bounds__(256) k_front(const float* __restrict__ NF,
                                               const int* __restrict__ EI,
                                               const float* __restrict__ AK) {
    __shared__ __align__(16) unsigned char sraw[64 * SA_LD * 2];  // 17408 B
    int t = threadIdx.x, b = blockIdx.x;

    if (b < HIST_BLOCKS) {                       // ---- dst histogram ----
        int e = b * 256 + t;
        int2 ei = reinterpret_cast<const int2*>(EI)[e];
        atomicAdd(&g_cnt[ei.y], 1);
        return;
    }

    // ---- GEMM tile: 64 rows of node_proj + ssrc scores ----
    int row0 = (b - HIST_BLOCKS) * 64;
    __half* sA = reinterpret_cast<__half*>(sraw);   // 64 x 128, stride SA_LD
    float*  sC = reinterpret_cast<float*>(sraw);    // 64 x 64 f32 (alias)

    // load + convert A tile (2048 float4), padded rows
#pragma unroll
    for (int i = 0; i < 8; i++) {
        int idx = i * 256 + t;
        int r = idx >> 5, c4 = idx & 31;
        int gr = row0 + r;
        float4 v = (gr < N_NODES)
            ? reinterpret_cast<const float4*>(NF)[(size_t)gr * 32 + c4]
            : make_float4(0.f, 0.f, 0.f, 0.f);
        __half2 h01 = __floats2half2_rn(v.x, v.y);
        __half2 h23 = __floats2half2_rn(v.z, v.w);
        uint2 raw;
        raw.x = *reinterpret_cast<unsigned*>(&h01);
        raw.y = *reinterpret_cast<unsigned*>(&h23);
        *reinterpret_cast<uint2*>(&sA[r * SA_LD + c4 * 4]) = raw;
    }
    __syncthreads();

    int w = t >> 5, wm = w >> 1, wn = w & 1;
    wmma::fragment<wmma::accumulator, 16, 16, 16, float> c[4];
#pragma unroll
    for (int j = 0; j < 4; j++) wmma::fill_fragment(c[j], 0.f);
#pragma unroll
    for (int k = 0; k < 8; k++) {
        wmma::fragment<wmma::matrix_a, 16, 16, 16, __half, wmma::row_major> a;
        wmma::load_matrix_sync(a, sA + (wm * 16) * SA_LD + k * 16, SA_LD);
#pragma unroll
        for (int j = 0; j < 4; j++) {
            wmma::fragment<wmma::matrix_b, 16, 16, 16, __half, wmma::row_major> bf;
            wmma::load_matrix_sync(bf, g_Wn_h + (k * 16) * 128 + wn * 64 + j * 16, 128);
            wmma::mma_sync(c[j], a, bf, c[j]);
        }
    }

    // two column-half passes through aliased sC
#pragma unroll
    for (int jh = 0; jh < 2; jh++) {
        __syncthreads();
        if (wn == jh) {
#pragma unroll
            for (int j = 0; j < 4; j++)
                wmma::store_matrix_sync(sC + (wm * 16) * 64 + j * 16, c[j],
                                        64, wmma::mem_row_major);
        }
        __syncthreads();
        // fp16 node_proj write (cols jh*64 .. jh*64+63)
#pragma unroll
        for (int i = 0; i < 8; i++) {
            int idx = i * 256 + t;
            int r = idx >> 5, c2 = idx & 31;
            int gr = row0 + r;
            if (gr < N_NODES) {
                float2 v = reinterpret_cast<const float2*>(sC)[r * 32 + c2];
                g_np_h[(size_t)gr * 64 + jh * 32 + c2] = __floats2half2_rn(v.x, v.y);
            }
        }
        // ssrc for heads jh*2, jh*2+1 (s_dst cancels in segment softmax)
        if (t < 128) {
            int r = t >> 1, hh = t & 1, h = jh * 2 + hh;
            int gr = row0 + r;
            if (gr < N_NODES) {
                const float4* akp = reinterpret_cast<const float4*>(AK + h * 96);
                const float4* cr = reinterpret_cast<const float4*>(sC + r * 64 + hh * 32);
                float s = 0.f;
#pragma unroll
                for (int k4 = 0; k4 < 8; k4++) {
                    float4 a = cr[k4];
                    float4 ak = akp[k4];
                    s += a.x * ak.x + a.y * ak.y + a.z * ak.z + a.w * ak.w;
                }
                g_ssrc[gr * 4 + h] = s;
            }
        }
    }
}

// ===== launch 2: single-pass decoupled-lookback scan -> rowptr + head =====
__global__ void __launch_bounds__(1024) k_scan() {
    __shared__ int s[1024];
    __shared__ int sprefix;
    int t = threadIdx.x, b = blockIdx.x;
    int i = b * 1024 + t;
    int v = (i < N_NODES) ? g_cnt[i] : 0;
    s[t] = v;
    __syncthreads();
    for (int o = 1; o < 1024; o <<= 1) {
        int u = (t >= o) ? s[t - o] : 0;
        __syncthreads();
        s[t] += u;
        __syncthreads();
    }
    int excl = s[t] - v;
    int total = s[1023];

    if (t == 0) {
        unsigned long long st = ((b == 0 ? 2ull : 1ull) << 32) | (unsigned)total;
        atomicExch(&g_state[b], st);
        if (b == 0) sprefix = 0;
    }
    if (b > 0 && t < 32) {
        int lane = t;
        unsigned running = 0;
        int idx = b - 1;
        while (true) {
            int pi = idx - lane;
            unsigned long long sv_ = (pi >= 0) ? atomicAdd(&g_state[pi], 0ull)
                                               : (2ull << 32);
            int flag = (int)(sv_ >> 32);
            unsigned val = (unsigned)sv_;
            unsigned m2 = __ballot_sync(FULLM, flag == 2);
            unsigned m0 = __ballot_sync(FULLM, flag == 0);
            int f2 = m2 ? (__ffs(m2) - 1) : 32;
            int f0 = m0 ? (__ffs(m0) - 1) : 32;
            if (f2 < f0) {
                unsigned cc = (lane <= f2) ? val : 0;
#pragma unroll
                for (int o = 16; o >= 1; o >>= 1) cc += __shfl_down_sync(FULLM, cc, o);
                if (lane == 0) running += cc;
                break;
            } else if (f0 < 32) {
                unsigned cc = (lane < f0) ? val : 0;
#pragma unroll
                for (int o = 16; o >= 1; o >>= 1) cc += __shfl_down_sync(FULLM, cc, o);
                if (lane == 0) running += cc;
                idx -= f0;
            } else {
                unsigned cc = val;
#pragma unroll
                for (int o = 16; o >= 1; o >>= 1) cc += __shfl_down_sync(FULLM, cc, o);
                if (lane == 0) running += cc;
                idx -= 32;
            }
        }
        if (lane == 0) {
            atomicExch(&g_state[b], (2ull << 32) | (unsigned)(running + total));
            sprefix = (int)running;
        }
    }
    __syncthreads();
    int P = sprefix;
    if (i < N_NODES) {
        int r = excl + P;
        g_rowptr[i] = r;
        g_head[i] = r;
    }
    if (b == 0 && t == 0) g_rowptr[N_NODES] = N_EDGES;
}

// ===== launch 3 (PROFILED): permute via wmma edge-score GEMM =====
// 256 edges/block: s_edge(256x4) = EF_h(256x32) @ V(32x16, 4 cols used)
__global__ void __launch_bounds__(256) k_permute(const int* __restrict__ EI,
                                                 const float* __restrict__ EF) {
    __shared__ __align__(16) unsigned char psm[21504];
    __half* sEFh = reinterpret_cast<__half*>(psm);        // 256x32 fp16 (16 KB)
    float*  sC   = reinterpret_cast<float*>(psm);         // 256x20 f32 (alias)
    __half* sV   = reinterpret_cast<__half*>(psm + 20480);// 32x16 fp16 (1 KB)
    int t = threadIdx.x, w = t >> 5;
    int e0 = blockIdx.x * 256;

    // early: edge endpoints + random ssrc gather (in flight during staging)
    int2 ei = reinterpret_cast<const int2*>(EI)[e0 + t];
    float4 ss4 = *reinterpret_cast<const float4*>(&g_ssrc[ei.x * 4]);

#pragma unroll
    for (int i = 0; i < 2; i++) {
        int idx = i * 256 + t;
        int k = idx >> 4, cn = idx & 15;
        sV[idx] = (cn < 4) ? __float2half_rn(g_v[cn * 32 + k]) : __ushort_as_half(0);
    }
#pragma unroll
    for (int i = 0; i < 8; i++) {
        int idx = i * 256 + t;
        int el = idx >> 3, c4 = idx & 7;
        float4 v = reinterpret_cast<const float4*>(EF)[(size_t)(e0 + el) * 8 + c4];
        __half2 ha = __floats2half2_rn(v.x, v.y);
        __half2 hb = __floats2half2_rn(v.z, v.w);
        uint2 raw;
        raw.x = *reinterpret_cast<unsigned*>(&ha);
        raw.y = *reinterpret_cast<unsigned*>(&hb);
        *reinterpret_cast<uint2*>(&sEFh[el * 32 + c4 * 4]) = raw;
    }
    __syncthreads();

    wmma::fragment<wmma::accumulator, 16, 16, 16, float> cf[2];
#pragma unroll
    for (int mi = 0; mi < 2; mi++) {
        int mt = 2 * w + mi;
        wmma::fill_fragment(cf[mi], 0.f);
#pragma unroll
        for (int kk = 0; kk < 2; kk++) {
            wmma::fragment<wmma::matrix_a, 16, 16, 16, __half, wmma::row_major> a;
            wmma::load_matrix_sync(a, sEFh + (mt * 16) * 32 + kk * 16, 32);
            wmma::fragment<wmma::matrix_b, 16, 16, 16, __half, wmma::row_major> bf;
            wmma::load_matrix_sync(bf, sV + (kk * 16) * 16, 16);
            wmma::mma_sync(cf[mi], a, bf, cf[mi]);
        }
    }
    __syncthreads();   // A fully consumed before aliasing writes
#pragma unroll
    for (int mi = 0; mi < 2; mi++)
        wmma::store_matrix_sync(sC + (2 * w + mi) * 16 * 20, cf[mi], 20,
                                wmma::mem_row_major);
    __syncthreads();

    float4 se = *reinterpret_cast<const float4*>(&sC[t * 20]);
    float4 p;
    p.x = __expf(ss4.x + se.x);
    p.y = __expf(ss4.y + se.y);
    p.z = __expf(ss4.z + se.z);
    p.w = __expf(ss4.w + se.w);
    int pos = atomicAdd(&g_head[ei.y], 1);
    g_p4[pos] = p;
    g_src[pos] = ei.x;
}

// ===== launch 4: gather-aggregate (16-lane pairs) + wmma out-GEMM + gelu ===
// block = 64 nodes; warp = 8 contiguous nodes; edges 16-lane rows (pairs).
__global__ void __launch_bounds__(256) k_agg_out(const float* __restrict__ bo,
                                                 float* __restrict__ out) {
    __shared__ __align__(16) unsigned char sm[27008];
    float*  s_p   = reinterpret_cast<float*>(sm);            // [2][8][32*4] 8 KB
    int*    s_srb = reinterpret_cast<int*>(sm + 8192);       // [2][8][32]   2 KB
    __half* s_Ah  = reinterpret_cast<__half*>(sm + 10240);   // [64][128]   16 KB
    float*  sD    = reinterpret_cast<float*>(sm);            // alias (epilogue)
    float*  sb    = reinterpret_cast<float*>(sm + 26624);    // 32 floats
    int t = threadIdx.x, lane = t & 31, w = t >> 5;

    // re-zero hist/scan state for the NEXT run
    {
        int zi = blockIdx.x * 256 + t;
        if (zi < N_NODES) g_cnt[zi] = 0;
        if (blockIdx.x == 0 && t < SCAN_BLOCKS) g_state[t] = 0ull;
    }
    if (t < 32) sb[t] = bo[t];

    int n0 = blockIdx.x * AGG_NPB;
    int nw0 = n0 + w * 8;
    int nw1 = min(nw0 + 8, N_NODES);

    if (nw0 < N_NODES) {
        int ebeg = g_rowptr[nw0];
        int eend = g_rowptr[nw1];
        int half = lane >> 4, li = lane & 15, h = li >> 2;
        const uint4* np4 = reinterpret_cast<const uint4*>(g_np_h);

        auto issue = [&](int cs) {
            int buf = ((cs - ebeg) >> 5) & 1;
            int j = cs + lane;
            if (j < eend) {
                unsigned ap = sm32(s_p + (buf * 8 + w) * 128 + lane * 4);
                asm volatile("cp.async.ca.shared.global [%0], [%1], 16;"
                             :: "r"(ap), "l"(g_p4 + j));
                unsigned as = sm32(s_srb + (buf * 8 + w) * 32 + lane);
                asm volatile("cp.async.ca.shared.global [%0], [%1], 4;"
                             :: "r"(as), "l"(g_src + j));
            }
            asm volatile("cp.async.commit_group;" ::: "memory");
        };

        if (ebeg < eend) {
            issue(ebeg);
            if (ebeg + 32 < eend) issue(ebeg + 32);
        }

        int j = ebeg;
        for (int n = nw0; n < nw1; n++) {
            int en = g_rowptr[n + 1];
            float acc[8] = {0.f, 0.f, 0.f, 0.f, 0.f, 0.f, 0.f, 0.f};
            float ds = 0.f;

            while (j < en) {
                int cb = ebeg + ((j - ebeg) & ~31);
                int ce = min(cb + 32, eend);
                if (j == cb) {
                    if (cb + 32 < eend) {
                        asm volatile("cp.async.wait_group 1;" ::: "memory");
                    } else {
                        asm volatile("cp.async.wait_group 0;" ::: "memory");
                    }
                    __syncwarp();
                }
                int buf = ((cb - ebeg) >> 5) & 1;
                const float* wp = s_p + (buf * 8 + w) * 128;
                const int* ws = s_srb + (buf * 8 + w) * 32;
                int stop = min(en, ce);
                int npair = (stop - j + 1) >> 1;
#pragma unroll 2
                for (int qp = 0; qp < npair; qp++) {
                    int e = j + qp * 2 + half;
                    bool valid = e < stop;
                    int qq = (e - ebeg) & 31;
                    int src = valid ? ws[qq] : 0;
                    float ph = valid ? wp[qq * 4 + h] : 0.f;
                    uint4 raw = np4[(size_t)src * 16 + li];
                    float2 f0 = __half22float2(*reinterpret_cast<__half2*>(&raw.x));
                    float2 f1 = __half22float2(*reinterpret_cast<__half2*>(&raw.y));
                    float2 f2 = __half22float2(*reinterpret_cast<__half2*>(&raw.z));
                    float2 f3 = __half22float2(*reinterpret_cast<__half2*>(&raw.w));
                    acc[0] += ph * f0.x; acc[1] += ph * f0.y;
                    acc[2] += ph * f1.x; acc[3] += ph * f1.y;
                    acc[4] += ph * f2.x; acc[5] += ph * f2.y;
                    acc[6] += ph * f3.x; acc[7] += ph * f3.y;
                    ds += ph;
                }
                j = stop;
                if (stop == ce) {
                    __syncwarp();
                    if (cb + 64 < eend) issue(cb + 64);
                }
            }

#pragma unroll
            for (int k = 0; k < 8; k++)
                acc[k] += __shfl_xor_sync(FULLM, acc[k], 16);
            ds += __shfl_xor_sync(FULLM, ds, 16);
            float inv = 1.f / (ds + 1e-8f);
            if (half == 0) {
                __half2 p0 = __floats2half2_rn(acc[0] * inv, acc[1] * inv);
                __half2 p1 = __floats2half2_rn(acc[2] * inv, acc[3] * inv);
                __half2 p2 = __floats2half2_rn(acc[4] * inv, acc[5] * inv);
                __half2 p3 = __floats2half2_rn(acc[6] * inv, acc[7] * inv);
                uint4 pk;
                pk.x = *reinterpret_cast<unsigned*>(&p0);
                pk.y = *reinterpret_cast<unsigned*>(&p1);
                pk.z = *reinterpret_cast<unsigned*>(&p2);
                pk.w = *reinterpret_cast<unsigned*>(&p3);
                *reinterpret_cast<uint4*>(&s_Ah[(n - n0) * 128 + li * 8]) = pk;
            }
        }
    }
    __syncthreads();

    // wmma epilogue: D(64x32) = A(64x128,fp16) @ Wo(128x32,fp16), fp32 acc
    {
        int mt = w & 3, nt = w >> 2;
        wmma::fragment<wmma::accumulator, 16, 16, 16, float> c;
        wmma::fill_fragment(c, 0.f);
#pragma unroll
        for (int kk = 0; kk < 8; kk++) {
            wmma::fragment<wmma::matrix_a, 16, 16, 16, __half, wmma::row_major> a;
            wmma::load_matrix_sync(a, s_Ah + (mt * 16) * 128 + kk * 16, 128);
            wmma::fragment<wmma::matrix_b, 16, 16, 16, __half, wmma::row_major> bf;
            wmma::load_matrix_sync(bf, g_Wo_h + (kk * 16) * 32 + nt * 16, 32);
            wmma::mma_sync(c, a, bf, c);
        }
        __syncthreads();
        wmma::store_matrix_sync(sD + (mt * 16) * 32 + nt * 16, c, 32,
                                wmma::mem_row_major);
    }
    __syncthreads();

    // gelu + coalesced store (512 float4)
#pragma unroll
    for (int i = 0; i < 2; i++) {
        int idx = i * 256 + t;
        int r = idx >> 3, c4 = idx & 7;
        int gn = n0 + r;
        if (gn < N_NODES) {
            float4 v = *reinterpret_cast<const float4*>(&sD[r * 32 + c4 * 4]);
            float4 bb = *reinterpret_cast<const float4*>(&sb[c4 * 4]);
            v.x += bb.x; v.y += bb.y; v.z += bb.z; v.w += bb.w;
            v.x = 0.5f * v.x * (1.f + erff(v.x * 0.70710678118f));
            v.y = 0.5f * v.y * (1.f + erff(v.y * 0.70710678118f));
            v.z = 0.5f * v.z * (1.f + erff(v.z * 0.70710678118f));
            v.w = 0.5f * v.w * (1.f + erff(v.w * 0.70710678118f));
            *reinterpret_cast<float4*>(&out[(size_t)gn * 32 + c4 * 4]) = v;
        }
    }
}

extern "C" void kernel_launch(void* const* d_in, const int* in_sizes, int n_in,
                              void* d_out, int out_size) {
    const float* NF = (const float*)d_in[0];   // node_features (N,128)
    const int*   EI = (const int*)  d_in[1];   // edge_index (E,2)
    const float* EF = (const float*)d_in[2];   // edge_features (E,32)
    const float* Wn = (const float*)d_in[3];   // W_node (128,128)
    const float* We = (const float*)d_in[4];   // W_edge (32,128)
    const float* AK = (const float*)d_in[5];   // attn_kernel (4,96)
    const float* Wo = (const float*)d_in[6];   // W_out (128,32)
    const float* bo = (const float*)d_in[7];   // b_out (32,)
    float* out = (float*)d_out;                // (N,32)

    k_fold<<<1, 256>>>(We, AK, Wo, Wn);
    k_front<<<HIST_BLOCKS + GEMM_TILES, 256>>>(NF, EI, AK);
    k_scan<<<SCAN_BLOCKS, 1024>>>();
    k_permute<<<N_EDGES / 256, 256>>>(EI, EF);   // profiled slot (index 3)
    k_agg_out<<<AGG_BLOCKS, 256>>>(bo, out);
}

// round 13
// speedup vs baseline: 1.0716x; 1.0341x over previous
#include <cuda_runtime.h>
#include <cuda_fp16.h>
#include <mma.h>
#include <math.h>

using namespace nvcuda;

#define N_NODES 100000
#define N_EDGES 1600000
#define F_IN    128
#define F_E     32
#define DH      128   // D*H
#define NH      4     // heads
#define FULLM   0xffffffffu
#define SCAN_BLOCKS 98          // ceil(100000/1024)
#define HIST_BLOCKS 6250        // 6250*256 = 1.6M edges
#define GEMM_TILES  1563        // ceil(100000/64)
#define AGG_NPB     64          // nodes per block in agg_out
#define AGG_BLOCKS  1563        // ceil(100000/64)
#define SA_LD       72          // padded stride (halves) for 64-wide A K-slice
#define SC_LD       132         // padded stride (floats) for 128-wide C tile

// -------- scratch (static device globals; zero-initialized at load) --------
__device__ __half2 g_np_h[(size_t)N_NODES * 64];      // node_proj fp16, 25.6 MB
__device__ float g_ssrc[N_NODES * NH];
__device__ float g_v[NH * F_E];                       // W_edge @ a_edge (per head)
__device__ __half g_Wo_h[DH * 32];                    // W_out in fp16
__device__ __half g_Wn_h[F_IN * DH];                  // W_node in fp16 (32 KB)
__device__ int g_cnt[N_NODES];                        // zeroed by prev run's agg_out
__device__ int g_rowptr[N_NODES + 1];
__device__ int g_head[N_NODES];
__device__ unsigned long long g_state[SCAN_BLOCKS];   // zeroed by prev run's agg_out
__device__ float4 g_p4[N_EDGES];                      // attn numerators, dst-sorted
__device__ int    g_src[N_EDGES];                     // src ids, dst-sorted

static __device__ __forceinline__ unsigned sm32(const void* p) {
    return (unsigned)__cvta_generic_to_shared(p);
}

// ===== launch 0: folds — v = We@a_edge, W_out -> fp16, W_node -> fp16 =====
__global__ void __launch_bounds__(256) k_fold(const float* __restrict__ We,
                                              const float* __restrict__ AK,
                                              const float* __restrict__ Wo,
                                              const float* __restrict__ Wn) {
    int t = threadIdx.x;
    if (t < 128) {
        int h = t >> 5, k = t & 31;
        float s = 0.f;
#pragma unroll
        for (int d = 0; d < 32; d++)
            s += We[k * DH + h * 32 + d] * AK[h * 96 + 64 + d];
        g_v[t] = s;
    }
#pragma unroll
    for (int i = 0; i < 16; i++) {
        int idx = i * 256 + t;
        g_Wo_h[idx] = __float2half_rn(Wo[idx]);
    }
#pragma unroll
    for (int i = 0; i < 32; i++) {              // 8192 half2
        int idx = i * 256 + t;
        float2 w2 = reinterpret_cast<const float2*>(Wn)[idx];
        reinterpret_cast<__half2*>(g_Wn_h)[idx] = __floats2half2_rn(w2.x, w2.y);
    }
}

// ===== launch 1: dst histogram =====
__global__ void __launch_bounds__(256) k_hist(const int* __restrict__ EI) {
    int e = blockIdx.x * 256 + threadIdx.x;
    int2 ei = reinterpret_cast<const int2*>(EI)[e];
    atomicAdd(&g_cnt[ei.y], 1);
}

// ===== launch 2: single-pass decoupled-lookback scan -> rowptr + head =====
__global__ void __launch_bounds__(1024) k_scan() {
    __shared__ int s[1024];
    __shared__ int sprefix;
    int t = threadIdx.x, b = blockIdx.x;
    int i = b * 1024 + t;
    int v = (i < N_NODES) ? g_cnt[i] : 0;
    s[t] = v;
    __syncthreads();
    for (int o = 1; o < 1024; o <<= 1) {
        int u = (t >= o) ? s[t - o] : 0;
        __syncthreads();
        s[t] += u;
        __syncthreads();
    }
    int excl = s[t] - v;
    int total = s[1023];

    if (t == 0) {
        unsigned long long st = ((b == 0 ? 2ull : 1ull) << 32) | (unsigned)total;
        atomicExch(&g_state[b], st);
        if (b == 0) sprefix = 0;
    }
    if (b > 0 && t < 32) {
        int lane = t;
        unsigned running = 0;
        int idx = b - 1;
        while (true) {
            int pi = idx - lane;
            unsigned long long sv_ = (pi >= 0) ? atomicAdd(&g_state[pi], 0ull)
                                               : (2ull << 32);
            int flag = (int)(sv_ >> 32);
            unsigned val = (unsigned)sv_;
            unsigned m2 = __ballot_sync(FULLM, flag == 2);
            unsigned m0 = __ballot_sync(FULLM, flag == 0);
            int f2 = m2 ? (__ffs(m2) - 1) : 32;
            int f0 = m0 ? (__ffs(m0) - 1) : 32;
            if (f2 < f0) {
                unsigned cc = (lane <= f2) ? val : 0;
#pragma unroll
                for (int o = 16; o >= 1; o >>= 1) cc += __shfl_down_sync(FULLM, cc, o);
                if (lane == 0) running += cc;
                break;
            } else if (f0 < 32) {
                unsigned cc = (lane < f0) ? val : 0;
#pragma unroll
                for (int o = 16; o >= 1; o >>= 1) cc += __shfl_down_sync(FULLM, cc, o);
                if (lane == 0) running += cc;
                idx -= f0;
            } else {
                unsigned cc = val;
#pragma unroll
                for (int o = 16; o >= 1; o >>= 1) cc += __shfl_down_sync(FULLM, cc, o);
                if (lane == 0) running += cc;
                idx -= 32;
            }
        }
        if (lane == 0) {
            atomicExch(&g_state[b], (2ull << 32) | (unsigned)(running + total));
            sprefix = (int)running;
        }
    }
    __syncthreads();
    int P = sprefix;
    if (i < N_NODES) {
        int r = excl + P;
        g_rowptr[i] = r;
        g_head[i] = r;
    }
    if (b == 0 && t == 0) g_rowptr[N_NODES] = N_EDGES;
}

// ===== launch 3 (PROFILED): node GEMM — K-split A, padded C, 1-pass epi ===
__global__ void __launch_bounds__(256) k_gemm(const float* __restrict__ NF,
                                              const float* __restrict__ AK) {
    __shared__ __align__(16) __half sA[64 * SA_LD];   // 9.2 KB (K-slice)
    __shared__ __align__(16) float  sC[64 * SC_LD];   // 33.8 KB (full C)
    int t = threadIdx.x;
    int row0 = blockIdx.x * 64;
    int w = t >> 5, wm = w >> 1, wn = w & 1;

    wmma::fragment<wmma::accumulator, 16, 16, 16, float> c[4];
#pragma unroll
    for (int j = 0; j < 4; j++) wmma::fill_fragment(c[j], 0.f);

#pragma unroll
    for (int kh = 0; kh < 2; kh++) {
        if (kh) __syncthreads();          // protect sA reuse
        // stage 64x64 fp16 K-slice of A (1024 float4 loads)
#pragma unroll
        for (int i = 0; i < 4; i++) {
            int idx = i * 256 + t;
            int r = idx >> 4, c4 = idx & 15;
            int gr = row0 + r;
            float4 v = (gr < N_NODES)
                ? reinterpret_cast<const float4*>(NF)[(size_t)gr * 32 + kh * 16 + c4]
                : make_float4(0.f, 0.f, 0.f, 0.f);
            __half2 h01 = __floats2half2_rn(v.x, v.y);
            __half2 h23 = __floats2half2_rn(v.z, v.w);
            uint2 raw;
            raw.x = *reinterpret_cast<unsigned*>(&h01);
            raw.y = *reinterpret_cast<unsigned*>(&h23);
            *reinterpret_cast<uint2*>(&sA[r * SA_LD + c4 * 4]) = raw;
        }
        __syncthreads();
#pragma unroll
        for (int k = 0; k < 4; k++) {
            wmma::fragment<wmma::matrix_a, 16, 16, 16, __half, wmma::row_major> a;
            wmma::load_matrix_sync(a, sA + (wm * 16) * SA_LD + k * 16, SA_LD);
#pragma unroll
            for (int j = 0; j < 4; j++) {
                wmma::fragment<wmma::matrix_b, 16, 16, 16, __half, wmma::row_major> bf;
                wmma::load_matrix_sync(bf,
                    g_Wn_h + ((kh * 4 + k) * 16) * 128 + wn * 64 + j * 16, 128);
                wmma::mma_sync(c[j], a, bf, c[j]);
            }
        }
    }

    // store all accumulators (padded, conflict-rotated), one sync
#pragma unroll
    for (int j = 0; j < 4; j++)
        wmma::store_matrix_sync(sC + (wm * 16) * SC_LD + wn * 64 + j * 16, c[j],
                                SC_LD, wmma::mem_row_major);
    __syncthreads();

    // epilogue A: node_proj fp16 (64 rows x 64 half2)
#pragma unroll
    for (int i = 0; i < 16; i++) {
        int idx = i * 256 + t;
        int r = idx >> 6, c2 = idx & 63;
        int gr = row0 + r;
        if (gr < N_NODES) {
            float2 v = *reinterpret_cast<const float2*>(&sC[r * SC_LD + c2 * 2]);
            g_np_h[(size_t)gr * 64 + c2] = __floats2half2_rn(v.x, v.y);
        }
    }
    // epilogue B: ssrc (all 256 threads: r = t>>2, h = t&3)
    {
        int r = t >> 2, h = t & 3;
        int gr = row0 + r;
        if (gr < N_NODES) {
            const float4* akp = reinterpret_cast<const float4*>(AK + h * 96);
            const float* cr = sC + r * SC_LD + h * 32;
            float s = 0.f;
#pragma unroll
            for (int k4 = 0; k4 < 8; k4++) {
                float4 a = *reinterpret_cast<const float4*>(&cr[k4 * 4]);
                float4 ak = akp[k4];
                s += a.x * ak.x + a.y * ak.y + a.z * ak.z + a.w * ak.w;
            }
            g_ssrc[gr * 4 + h] = s;
        }
    }
}

// ===== launch 4: permute via wmma edge-score GEMM =====
// 256 edges/block: s_edge(256x4) = EF_h(256x32) @ V(32x16, 4 cols used)
__global__ void __launch_bounds__(256) k_permute(const int* __restrict__ EI,
                                                 const float* __restrict__ EF) {
    __shared__ __align__(16) unsigned char psm[21504];
    __half* sEFh = reinterpret_cast<__half*>(psm);        // 256x32 fp16 (16 KB)
    float*  sC   = reinterpret_cast<float*>(psm);         // 256x20 f32 (alias)
    __half* sV   = reinterpret_cast<__half*>(psm + 20480);// 32x16 fp16 (1 KB)
    int t = threadIdx.x, w = t >> 5;
    int e0 = blockIdx.x * 256;

    // early: edge endpoints + random ssrc gather (in flight during staging)
    int2 ei = reinterpret_cast<const int2*>(EI)[e0 + t];
    float4 ss4 = *reinterpret_cast<const float4*>(&g_ssrc[ei.x * 4]);

#pragma unroll
    for (int i = 0; i < 2; i++) {
        int idx = i * 256 + t;
        int k = idx >> 4, cn = idx & 15;
        sV[idx] = (cn < 4) ? __float2half_rn(g_v[cn * 32 + k]) : __ushort_as_half(0);
    }
#pragma unroll
    for (int i = 0; i < 8; i++) {
        int idx = i * 256 + t;
        int el = idx >> 3, c4 = idx & 7;
        float4 v = reinterpret_cast<const float4*>(EF)[(size_t)(e0 + el) * 8 + c4];
        __half2 ha = __floats2half2_rn(v.x, v.y);
        __half2 hb = __floats2half2_rn(v.z, v.w);
        uint2 raw;
        raw.x = *reinterpret_cast<unsigned*>(&ha);
        raw.y = *reinterpret_cast<unsigned*>(&hb);
        *reinterpret_cast<uint2*>(&sEFh[el * 32 + c4 * 4]) = raw;
    }
    __syncthreads();

    wmma::fragment<wmma::accumulator, 16, 16, 16, float> cf[2];
#pragma unroll
    for (int mi = 0; mi < 2; mi++) {
        int mt = 2 * w + mi;
        wmma::fill_fragment(cf[mi], 0.f);
#pragma unroll
        for (int kk = 0; kk < 2; kk++) {
            wmma::fragment<wmma::matrix_a, 16, 16, 16, __half, wmma::row_major> a;
            wmma::load_matrix_sync(a, sEFh + (mt * 16) * 32 + kk * 16, 32);
            wmma::fragment<wmma::matrix_b, 16, 16, 16, __half, wmma::row_major> bf;
            wmma::load_matrix_sync(bf, sV + (kk * 16) * 16, 16);
            wmma::mma_sync(cf[mi], a, bf, cf[mi]);
        }
    }
    __syncthreads();   // A fully consumed before aliasing writes
#pragma unroll
    for (int mi = 0; mi < 2; mi++)
        wmma::store_matrix_sync(sC + (2 * w + mi) * 16 * 20, cf[mi], 20,
                                wmma::mem_row_major);
    __syncthreads();

    float4 se = *reinterpret_cast<const float4*>(&sC[t * 20]);
    float4 p;
    p.x = __expf(ss4.x + se.x);
    p.y = __expf(ss4.y + se.y);
    p.z = __expf(ss4.z + se.z);
    p.w = __expf(ss4.w + se.w);
    int pos = atomicAdd(&g_head[ei.y], 1);
    g_p4[pos] = p;
    g_src[pos] = ei.x;
}

// ===== launch 5: gather-aggregate (16-lane pairs) + wmma out-GEMM + gelu ===
// block = 64 nodes; warp = 8 contiguous nodes; edges 16-lane rows (pairs).
__global__ void __launch_bounds__(256) k_agg_out(const float* __restrict__ bo,
                                                 float* __restrict__ out) {
    __shared__ __align__(16) unsigned char sm[27008];
    float*  s_p   = reinterpret_cast<float*>(sm);            // [2][8][32*4] 8 KB
    int*    s_srb = reinterpret_cast<int*>(sm + 8192);       // [2][8][32]   2 KB
    __half* s_Ah  = reinterpret_cast<__half*>(sm + 10240);   // [64][128]   16 KB
    float*  sD    = reinterpret_cast<float*>(sm);            // alias (epilogue)
    float*  sb    = reinterpret_cast<float*>(sm + 26624);    // 32 floats
    int t = threadIdx.x, lane = t & 31, w = t >> 5;

    // re-zero hist/scan state for the NEXT run
    {
        int zi = blockIdx.x * 256 + t;
        if (zi < N_NODES) g_cnt[zi] = 0;
        if (blockIdx.x == 0 && t < SCAN_BLOCKS) g_state[t] = 0ull;
    }
    if (t < 32) sb[t] = bo[t];

    int n0 = blockIdx.x * AGG_NPB;
    int nw0 = n0 + w * 8;
    int nw1 = min(nw0 + 8, N_NODES);

    if (nw0 < N_NODES) {
        int ebeg = g_rowptr[nw0];
        int eend = g_rowptr[nw1];
        int half = lane >> 4, li = lane & 15, h = li >> 2;
        const uint4* np4 = reinterpret_cast<const uint4*>(g_np_h);

        auto issue = [&](int cs) {
            int buf = ((cs - ebeg) >> 5) & 1;
            int j = cs + lane;
            if (j < eend) {
                unsigned ap = sm32(s_p + (buf * 8 + w) * 128 + lane * 4);
                asm volatile("cp.async.ca.shared.global [%0], [%1], 16;"
                             :: "r"(ap), "l"(g_p4 + j));
                unsigned as = sm32(s_srb + (buf * 8 + w) * 32 + lane);
                asm volatile("cp.async.ca.shared.global [%0], [%1], 4;"
                             :: "r"(as), "l"(g_src + j));
            }
            asm volatile("cp.async.commit_group;" ::: "memory");
        };

        if (ebeg < eend) {
            issue(ebeg);
            if (ebeg + 32 < eend) issue(ebeg + 32);
        }

        int j = ebeg;
        for (int n = nw0; n < nw1; n++) {
            int en = g_rowptr[n + 1];
            float acc[8] = {0.f, 0.f, 0.f, 0.f, 0.f, 0.f, 0.f, 0.f};
            float ds = 0.f;

            while (j < en) {
                int cb = ebeg + ((j - ebeg) & ~31);
                int ce = min(cb + 32, eend);
                if (j == cb) {
                    if (cb + 32 < eend) {
                        asm volatile("cp.async.wait_group 1;" ::: "memory");
                    } else {
                        asm volatile("cp.async.wait_group 0;" ::: "memory");
                    }
                    __syncwarp();
                }
                int buf = ((cb - ebeg) >> 5) & 1;
                const float* wp = s_p + (buf * 8 + w) * 128;
                const int* ws = s_srb + (buf * 8 + w) * 32;
                int stop = min(en, ce);
                int npair = (stop - j + 1) >> 1;
#pragma unroll 2
                for (int qp = 0; qp < npair; qp++) {
                    int e = j + qp * 2 + half;
                    bool valid = e < stop;
                    int qq = (e - ebeg) & 31;
                    int src = valid ? ws[qq] : 0;
                    float ph = valid ? wp[qq * 4 + h] : 0.f;
                    uint4 raw = np4[(size_t)src * 16 + li];
                    float2 f0 = __half22float2(*reinterpret_cast<__half2*>(&raw.x));
                    float2 f1 = __half22float2(*reinterpret_cast<__half2*>(&raw.y));
                    float2 f2 = __half22float2(*reinterpret_cast<__half2*>(&raw.z));
                    float2 f3 = __half22float2(*reinterpret_cast<__half2*>(&raw.w));
                    acc[0] += ph * f0.x; acc[1] += ph * f0.y;
                    acc[2] += ph * f1.x; acc[3] += ph * f1.y;
                    acc[4] += ph * f2.x; acc[5] += ph * f2.y;
                    acc[6] += ph * f3.x; acc[7] += ph * f3.y;
                    ds += ph;
                }
                j = stop;
                if (stop == ce) {
                    __syncwarp();
                    if (cb + 64 < eend) issue(cb + 64);
                }
            }

#pragma unroll
            for (int k = 0; k < 8; k++)
                acc[k] += __shfl_xor_sync(FULLM, acc[k], 16);
            ds += __shfl_xor_sync(FULLM, ds, 16);
            float inv = 1.f / (ds + 1e-8f);
            if (half == 0) {
                __half2 p0 = __floats2half2_rn(acc[0] * inv, acc[1] * inv);
                __half2 p1 = __floats2half2_rn(acc[2] * inv, acc[3] * inv);
                __half2 p2 = __floats2half2_rn(acc[4] * inv, acc[5] * inv);
                __half2 p3 = __floats2half2_rn(acc[6] * inv, acc[7] * inv);
                uint4 pk;
                pk.x = *reinterpret_cast<unsigned*>(&p0);
                pk.y = *reinterpret_cast<unsigned*>(&p1);
                pk.z = *reinterpret_cast<unsigned*>(&p2);
                pk.w = *reinterpret_cast<unsigned*>(&p3);
                *reinterpret_cast<uint4*>(&s_Ah[(n - n0) * 128 + li * 8]) = pk;
            }
        }
    }
    __syncthreads();

    // wmma epilogue: D(64x32) = A(64x128,fp16) @ Wo(128x32,fp16), fp32 acc
    {
        int mt = w & 3, nt = w >> 2;
        wmma::fragment<wmma::accumulator, 16, 16, 16, float> c;
        wmma::fill_fragment(c, 0.f);
#pragma unroll
        for (int kk = 0; kk < 8; kk++) {
            wmma::fragment<wmma::matrix_a, 16, 16, 16, __half, wmma::row_major> a;
            wmma::load_matrix_sync(a, s_Ah + (mt * 16) * 128 + kk * 16, 128);
            wmma::fragment<wmma::matrix_b, 16, 16, 16, __half, wmma::row_major> bf;
            wmma::load_matrix_sync(bf, g_Wo_h + (kk * 16) * 32 + nt * 16, 32);
            wmma::mma_sync(c, a, bf, c);
        }
        __syncthreads();
        wmma::store_matrix_sync(sD + (mt * 16) * 32 + nt * 16, c, 32,
                                wmma::mem_row_major);
    }
    __syncthreads();

    // gelu + coalesced store (512 float4)
#pragma unroll
    for (int i = 0; i < 2; i++) {
        int idx = i * 256 + t;
        int r = idx >> 3, c4 = idx & 7;
        int gn = n0 + r;
        if (gn < N_NODES) {
            float4 v = *reinterpret_cast<const float4*>(&sD[r * 32 + c4 * 4]);
            float4 bb = *reinterpret_cast<const float4*>(&sb[c4 * 4]);
            v.x += bb.x; v.y += bb.y; v.z += bb.z; v.w += bb.w;
            v.x = 0.5f * v.x * (1.f + erff(v.x * 0.70710678118f));
            v.y = 0.5f * v.y * (1.f + erff(v.y * 0.70710678118f));
            v.z = 0.5f * v.z * (1.f + erff(v.z * 0.70710678118f));
            v.w = 0.5f * v.w * (1.f + erff(v.w * 0.70710678118f));
            *reinterpret_cast<float4*>(&out[(size_t)gn * 32 + c4 * 4]) = v;
        }
    }
}

extern "C" void kernel_launch(void* const* d_in, const int* in_sizes, int n_in,
                              void* d_out, int out_size) {
    const float* NF = (const float*)d_in[0];   // node_features (N,128)
    const int*   EI = (const int*)  d_in[1];   // edge_index (E,2)
    const float* EF = (const float*)d_in[2];   // edge_features (E,32)
    const float* Wn = (const float*)d_in[3];   // W_node (128,128)
    const float* We = (const float*)d_in[4];   // W_edge (32,128)
    const float* AK = (const float*)d_in[5];   // attn_kernel (4,96)
    const float* Wo = (const float*)d_in[6];   // W_out (128,32)
    const float* bo = (const float*)d_in[7];   // b_out (32,)
    float* out = (float*)d_out;                // (N,32)

    k_fold<<<1, 256>>>(We, AK, Wo, Wn);
    k_hist<<<HIST_BLOCKS, 256>>>(EI);
    k_scan<<<SCAN_BLOCKS, 1024>>>();
    k_gemm<<<GEMM_TILES, 256>>>(NF, AK);         // profiled slot (index 3)
    k_permute<<<N_EDGES / 256, 256>>>(EI, EF);
    k_agg_out<<<AGG_BLOCKS, 256>>>(bo, out);
}

// round 14
// speedup vs baseline: 1.2925x; 1.2061x over previous
#include <cuda_runtime.h>
#include <cuda_fp16.h>
#include <mma.h>
#include <math.h>

using namespace nvcuda;

#define N_NODES 100000
#define N_EDGES 1600000
#define F_IN    128
#define F_E     32
#define DH      128   // D*H
#define NH      4     // heads
#define FULLM   0xffffffffu
#define SCAN_BLOCKS 98          // ceil(100000/1024)
#define HIST_BLOCKS 6250        // 6250*256 = 1.6M edges
#define GEMM_TILES  1563        // ceil(100000/64)
#define AGG_NPB     64          // nodes per block in agg_out
#define AGG_BLOCKS  1563        // ceil(100000/64)
#define SA_LD       72          // padded stride (halves) for 64-wide A K-slice
#define SB_LD       136         // padded stride (halves) for B tile (272B -> CF LDSM)
#define SC_LD       132         // padded stride (floats) for 128-wide C tile

// -------- scratch (static device globals; zero-initialized at load) --------
__device__ __half2 g_np_h[(size_t)N_NODES * 64];      // node_proj fp16, 25.6 MB
__device__ float g_ssrc[N_NODES * NH];
__device__ float g_v[NH * F_E];                       // W_edge @ a_edge (per head)
__device__ __half g_Wo_h[DH * 32];                    // W_out in fp16
__device__ __half g_Wn_h[F_IN * DH];                  // W_node in fp16 (32 KB)
__device__ int g_cnt[N_NODES];                        // zeroed by prev run's agg_out
__device__ int g_rowptr[N_NODES + 1];
__device__ int g_head[N_NODES];
__device__ unsigned long long g_state[SCAN_BLOCKS];   // zeroed by prev run's agg_out
__device__ float4 g_p4[N_EDGES];                      // attn numerators, dst-sorted
__device__ int    g_src[N_EDGES];                     // src ids, dst-sorted

static __device__ __forceinline__ unsigned sm32(const void* p) {
    return (unsigned)__cvta_generic_to_shared(p);
}

// ===== launch 0: folds — v = We@a_edge, W_out -> fp16, W_node -> fp16 =====
__global__ void __launch_bounds__(256) k_fold(const float* __restrict__ We,
                                              const float* __restrict__ AK,
                                              const float* __restrict__ Wo,
                                              const float* __restrict__ Wn) {
    int t = threadIdx.x;
    if (t < 128) {
        int h = t >> 5, k = t & 31;
        float s = 0.f;
#pragma unroll
        for (int d = 0; d < 32; d++)
            s += We[k * DH + h * 32 + d] * AK[h * 96 + 64 + d];
        g_v[t] = s;
    }
#pragma unroll
    for (int i = 0; i < 16; i++) {
        int idx = i * 256 + t;
        g_Wo_h[idx] = __float2half_rn(Wo[idx]);
    }
#pragma unroll
    for (int i = 0; i < 32; i++) {              // 8192 half2
        int idx = i * 256 + t;
        float2 w2 = reinterpret_cast<const float2*>(Wn)[idx];
        reinterpret_cast<__half2*>(g_Wn_h)[idx] = __floats2half2_rn(w2.x, w2.y);
    }
}

// ===== launch 1: dst histogram =====
__global__ void __launch_bounds__(256) k_hist(const int* __restrict__ EI) {
    int e = blockIdx.x * 256 + threadIdx.x;
    int2 ei = reinterpret_cast<const int2*>(EI)[e];
    atomicAdd(&g_cnt[ei.y], 1);
}

// ===== launch 2: single-pass decoupled-lookback scan -> rowptr + head =====
__global__ void __launch_bounds__(1024) k_scan() {
    __shared__ int s[1024];
    __shared__ int sprefix;
    int t = threadIdx.x, b = blockIdx.x;
    int i = b * 1024 + t;
    int v = (i < N_NODES) ? g_cnt[i] : 0;
    s[t] = v;
    __syncthreads();
    for (int o = 1; o < 1024; o <<= 1) {
        int u = (t >= o) ? s[t - o] : 0;
        __syncthreads();
        s[t] += u;
        __syncthreads();
    }
    int excl = s[t] - v;
    int total = s[1023];

    if (t == 0) {
        unsigned long long st = ((b == 0 ? 2ull : 1ull) << 32) | (unsigned)total;
        atomicExch(&g_state[b], st);
        if (b == 0) sprefix = 0;
    }
    if (b > 0 && t < 32) {
        int lane = t;
        unsigned running = 0;
        int idx = b - 1;
        while (true) {
            int pi = idx - lane;
            unsigned long long sv_ = (pi >= 0) ? atomicAdd(&g_state[pi], 0ull)
                                               : (2ull << 32);
            int flag = (int)(sv_ >> 32);
            unsigned val = (unsigned)sv_;
            unsigned m2 = __ballot_sync(FULLM, flag == 2);
            unsigned m0 = __ballot_sync(FULLM, flag == 0);
            int f2 = m2 ? (__ffs(m2) - 1) : 32;
            int f0 = m0 ? (__ffs(m0) - 1) : 32;
            if (f2 < f0) {
                unsigned cc = (lane <= f2) ? val : 0;
#pragma unroll
                for (int o = 16; o >= 1; o >>= 1) cc += __shfl_down_sync(FULLM, cc, o);
                if (lane == 0) running += cc;
                break;
            } else if (f0 < 32) {
                unsigned cc = (lane < f0) ? val : 0;
#pragma unroll
                for (int o = 16; o >= 1; o >>= 1) cc += __shfl_down_sync(FULLM, cc, o);
                if (lane == 0) running += cc;
                idx -= f0;
            } else {
                unsigned cc = val;
#pragma unroll
                for (int o = 16; o >= 1; o >>= 1) cc += __shfl_down_sync(FULLM, cc, o);
                if (lane == 0) running += cc;
                idx -= 32;
            }
        }
        if (lane == 0) {
            atomicExch(&g_state[b], (2ull << 32) | (unsigned)(running + total));
            sprefix = (int)running;
        }
    }
    __syncthreads();
    int P = sprefix;
    if (i < N_NODES) {
        int r = excl + P;
        g_rowptr[i] = r;
        g_head[i] = r;
    }
    if (b == 0 && t == 0) g_rowptr[N_NODES] = N_EDGES;
}

// ===== launch 3 (PROFILED): node GEMM — padded smem B (CF LDSM) =====
__global__ void __launch_bounds__(256) k_gemm(const float* __restrict__ NF,
                                              const float* __restrict__ AK) {
    __shared__ __align__(16) __half sB[128 * SB_LD];  // 34816 B (aliased by sC)
    __shared__ __align__(16) __half sA[64 * SA_LD];   // 9216 B
    float* sC = reinterpret_cast<float*>(sB);         // 64 x SC_LD f32 (33792 B)
    int t = threadIdx.x;
    int row0 = blockIdx.x * 64;
    int w = t >> 5, wm = w >> 1, wn = w & 1;

    // stage B once: 128x128 halves from L1-resident g_Wn_h, padded rows
#pragma unroll
    for (int i = 0; i < 8; i++) {
        int idx = i * 256 + t;                 // uint4 index (2048 total)
        int r = idx >> 4, c8 = idx & 15;
        uint4 v = reinterpret_cast<const uint4*>(g_Wn_h)[idx];
        *reinterpret_cast<uint4*>(&sB[r * SB_LD + c8 * 8]) = v;
    }

    wmma::fragment<wmma::accumulator, 16, 16, 16, float> c[4];
#pragma unroll
    for (int j = 0; j < 4; j++) wmma::fill_fragment(c[j], 0.f);

#pragma unroll
    for (int kh = 0; kh < 2; kh++) {
        if (kh) __syncthreads();          // protect sA reuse
        // stage 64x64 fp16 K-slice of A (1024 float4 loads)
#pragma unroll
        for (int i = 0; i < 4; i++) {
            int idx = i * 256 + t;
            int r = idx >> 4, c4 = idx & 15;
            int gr = row0 + r;
            float4 v = (gr < N_NODES)
                ? reinterpret_cast<const float4*>(NF)[(size_t)gr * 32 + kh * 16 + c4]
                : make_float4(0.f, 0.f, 0.f, 0.f);
            __half2 h01 = __floats2half2_rn(v.x, v.y);
            __half2 h23 = __floats2half2_rn(v.z, v.w);
            uint2 raw;
            raw.x = *reinterpret_cast<unsigned*>(&h01);
            raw.y = *reinterpret_cast<unsigned*>(&h23);
            *reinterpret_cast<uint2*>(&sA[r * SA_LD + c4 * 4]) = raw;
        }
        __syncthreads();
#pragma unroll
        for (int k = 0; k < 4; k++) {
            wmma::fragment<wmma::matrix_a, 16, 16, 16, __half, wmma::row_major> a;
            wmma::load_matrix_sync(a, sA + (wm * 16) * SA_LD + k * 16, SA_LD);
#pragma unroll
            for (int j = 0; j < 4; j++) {
                wmma::fragment<wmma::matrix_b, 16, 16, 16, __half, wmma::row_major> bf;
                wmma::load_matrix_sync(bf,
                    sB + ((kh * 4 + k) * 16) * SB_LD + wn * 64 + j * 16, SB_LD);
                wmma::mma_sync(c[j], a, bf, c[j]);
            }
        }
    }
    __syncthreads();   // all mma done before sC aliases sB

    // store all accumulators (padded, conflict-rotated), one sync
#pragma unroll
    for (int j = 0; j < 4; j++)
        wmma::store_matrix_sync(sC + (wm * 16) * SC_LD + wn * 64 + j * 16, c[j],
                                SC_LD, wmma::mem_row_major);
    __syncthreads();

    // epilogue A: node_proj fp16 (64 rows x 64 half2)
#pragma unroll
    for (int i = 0; i < 16; i++) {
        int idx = i * 256 + t;
        int r = idx >> 6, c2 = idx & 63;
        int gr = row0 + r;
        if (gr < N_NODES) {
            float2 v = *reinterpret_cast<const float2*>(&sC[r * SC_LD + c2 * 2]);
            g_np_h[(size_t)gr * 64 + c2] = __floats2half2_rn(v.x, v.y);
        }
    }
    // epilogue B: ssrc (all 256 threads: r = t>>2, h = t&3)
    {
        int r = t >> 2, h = t & 3;
        int gr = row0 + r;
        if (gr < N_NODES) {
            const float4* akp = reinterpret_cast<const float4*>(AK + h * 96);
            const float* cr = sC + r * SC_LD + h * 32;
            float s = 0.f;
#pragma unroll
            for (int k4 = 0; k4 < 8; k4++) {
                float4 a = *reinterpret_cast<const float4*>(&cr[k4 * 4]);
                float4 ak = akp[k4];
                s += a.x * ak.x + a.y * ak.y + a.z * ak.z + a.w * ak.w;
            }
            g_ssrc[gr * 4 + h] = s;
        }
    }
}

// ===== launch 4: permute via wmma edge-score GEMM =====
// 256 edges/block: s_edge(256x4) = EF_h(256x32) @ V(32x16, 4 cols used)
__global__ void __launch_bounds__(256) k_permute(const int* __restrict__ EI,
                                                 const float* __restrict__ EF) {
    __shared__ __align__(16) unsigned char psm[21504];
    __half* sEFh = reinterpret_cast<__half*>(psm);        // 256x32 fp16 (16 KB)
    float*  sC   = reinterpret_cast<float*>(psm);         // 256x20 f32 (alias)
    __half* sV   = reinterpret_cast<__half*>(psm + 20480);// 32x16 fp16 (1 KB)
    int t = threadIdx.x, w = t >> 5;
    int e0 = blockIdx.x * 256;

    // early: edge endpoints + random ssrc gather (in flight during staging)
    int2 ei = reinterpret_cast<const int2*>(EI)[e0 + t];
    float4 ss4 = *reinterpret_cast<const float4*>(&g_ssrc[ei.x * 4]);

#pragma unroll
    for (int i = 0; i < 2; i++) {
        int idx = i * 256 + t;
        int k = idx >> 4, cn = idx & 15;
        sV[idx] = (cn < 4) ? __float2half_rn(g_v[cn * 32 + k]) : __ushort_as_half(0);
    }
#pragma unroll
    for (int i = 0; i < 8; i++) {
        int idx = i * 256 + t;
        int el = idx >> 3, c4 = idx & 7;
        float4 v = reinterpret_cast<const float4*>(EF)[(size_t)(e0 + el) * 8 + c4];
        __half2 ha = __floats2half2_rn(v.x, v.y);
        __half2 hb = __floats2half2_rn(v.z, v.w);
        uint2 raw;
        raw.x = *reinterpret_cast<unsigned*>(&ha);
        raw.y = *reinterpret_cast<unsigned*>(&hb);
        *reinterpret_cast<uint2*>(&sEFh[el * 32 + c4 * 4]) = raw;
    }
    __syncthreads();

    wmma::fragment<wmma::accumulator, 16, 16, 16, float> cf[2];
#pragma unroll
    for (int mi = 0; mi < 2; mi++) {
        int mt = 2 * w + mi;
        wmma::fill_fragment(cf[mi], 0.f);
#pragma unroll
        for (int kk = 0; kk < 2; kk++) {
            wmma::fragment<wmma::matrix_a, 16, 16, 16, __half, wmma::row_major> a;
            wmma::load_matrix_sync(a, sEFh + (mt * 16) * 32 + kk * 16, 32);
            wmma::fragment<wmma::matrix_b, 16, 16, 16, __half, wmma::row_major> bf;
            wmma::load_matrix_sync(bf, sV + (kk * 16) * 16, 16);
            wmma::mma_sync(cf[mi], a, bf, cf[mi]);
        }
    }
    __syncthreads();   // A fully consumed before aliasing writes
#pragma unroll
    for (int mi = 0; mi < 2; mi++)
        wmma::store_matrix_sync(sC + (2 * w + mi) * 16 * 20, cf[mi], 20,
                                wmma::mem_row_major);
    __syncthreads();

    float4 se = *reinterpret_cast<const float4*>(&sC[t * 20]);
    float4 p;
    p.x = __expf(ss4.x + se.x);
    p.y = __expf(ss4.y + se.y);
    p.z = __expf(ss4.z + se.z);
    p.w = __expf(ss4.w + se.w);
    int pos = atomicAdd(&g_head[ei.y], 1);
    g_p4[pos] = p;
    g_src[pos] = ei.x;
}

// ===== launch 5: gather-aggregate (16-lane pairs) + wmma out-GEMM + gelu ===
// block = 64 nodes; warp = 8 contiguous nodes; edges 16-lane rows (pairs).
__global__ void __launch_bounds__(256) k_agg_out(const float* __restrict__ bo,
                                                 float* __restrict__ out) {
    __shared__ __align__(16) unsigned char sm[27008];
    float*  s_p   = reinterpret_cast<float*>(sm);            // [2][8][32*4] 8 KB
    int*    s_srb = reinterpret_cast<int*>(sm + 8192);       // [2][8][32]   2 KB
    __half* s_Ah  = reinterpret_cast<__half*>(sm + 10240);   // [64][128]   16 KB
    float*  sD    = reinterpret_cast<float*>(sm);            // alias (epilogue)
    float*  sb    = reinterpret_cast<float*>(sm + 26624);    // 32 floats
    int t = threadIdx.x, lane = t & 31, w = t >> 5;

    // re-zero hist/scan state for the NEXT run
    {
        int zi = blockIdx.x * 256 + t;
        if (zi < N_NODES) g_cnt[zi] = 0;
        if (blockIdx.x == 0 && t < SCAN_BLOCKS) g_state[t] = 0ull;
    }
    if (t < 32) sb[t] = bo[t];

    int n0 = blockIdx.x * AGG_NPB;
    int nw0 = n0 + w * 8;
    int nw1 = min(nw0 + 8, N_NODES);

    if (nw0 < N_NODES) {
        int ebeg = g_rowptr[nw0];
        int eend = g_rowptr[nw1];
        int half = lane >> 4, li = lane & 15, h = li >> 2;
        const uint4* np4 = reinterpret_cast<const uint4*>(g_np_h);

        auto issue = [&](int cs) {
            int buf = ((cs - ebeg) >> 5) & 1;
            int j = cs + lane;
            if (j < eend) {
                unsigned ap = sm32(s_p + (buf * 8 + w) * 128 + lane * 4);
                asm volatile("cp.async.ca.shared.global [%0], [%1], 16;"
                             :: "r"(ap), "l"(g_p4 + j));
                unsigned as = sm32(s_srb + (buf * 8 + w) * 32 + lane);
                asm volatile("cp.async.ca.shared.global [%0], [%1], 4;"
                             :: "r"(as), "l"(g_src + j));
            }
            asm volatile("cp.async.commit_group;" ::: "memory");
        };

        if (ebeg < eend) {
            issue(ebeg);
            if (ebeg + 32 < eend) issue(ebeg + 32);
        }

        int j = ebeg;
        for (int n = nw0; n < nw1; n++) {
            int en = g_rowptr[n + 1];
            float acc[8] = {0.f, 0.f, 0.f, 0.f, 0.f, 0.f, 0.f, 0.f};
            float ds = 0.f;

            while (j < en) {
                int cb = ebeg + ((j - ebeg) & ~31);
                int ce = min(cb + 32, eend);
                if (j == cb) {
                    if (cb + 32 < eend) {
                        asm volatile("cp.async.wait_group 1;" ::: "memory");
                    } else {
                        asm volatile("cp.async.wait_group 0;" ::: "memory");
                    }
                    __syncwarp();
                }
                int buf = ((cb - ebeg) >> 5) & 1;
                const float* wp = s_p + (buf * 8 + w) * 128;
                const int* ws = s_srb + (buf * 8 + w) * 32;
                int stop = min(en, ce);
                int npair = (stop - j + 1) >> 1;
#pragma unroll 2
                for (int qp = 0; qp < npair; qp++) {
                    int e = j + qp * 2 + half;
                    bool valid = e < stop;
                    int qq = (e - ebeg) & 31;
                    int src = valid ? ws[qq] : 0;
                    float ph = valid ? wp[qq * 4 + h] : 0.f;
                    uint4 raw = np4[(size_t)src * 16 + li];
                    float2 f0 = __half22float2(*reinterpret_cast<__half2*>(&raw.x));
                    float2 f1 = __half22float2(*reinterpret_cast<__half2*>(&raw.y));
                    float2 f2 = __half22float2(*reinterpret_cast<__half2*>(&raw.z));
                    float2 f3 = __half22float2(*reinterpret_cast<__half2*>(&raw.w));
                    acc[0] += ph * f0.x; acc[1] += ph * f0.y;
                    acc[2] += ph * f1.x; acc[3] += ph * f1.y;
                    acc[4] += ph * f2.x; acc[5] += ph * f2.y;
                    acc[6] += ph * f3.x; acc[7] += ph * f3.y;
                    ds += ph;
                }
                j = stop;
                if (stop == ce) {
                    __syncwarp();
                    if (cb + 64 < eend) issue(cb + 64);
                }
            }

#pragma unroll
            for (int k = 0; k < 8; k++)
                acc[k] += __shfl_xor_sync(FULLM, acc[k], 16);
            ds += __shfl_xor_sync(FULLM, ds, 16);
            float inv = 1.f / (ds + 1e-8f);
            if (half == 0) {
                __half2 p0 = __floats2half2_rn(acc[0] * inv, acc[1] * inv);
                __half2 p1 = __floats2half2_rn(acc[2] * inv, acc[3] * inv);
                __half2 p2 = __floats2half2_rn(acc[4] * inv, acc[5] * inv);
                __half2 p3 = __floats2half2_rn(acc[6] * inv, acc[7] * inv);
                uint4 pk;
                pk.x = *reinterpret_cast<unsigned*>(&p0);
                pk.y = *reinterpret_cast<unsigned*>(&p1);
                pk.z = *reinterpret_cast<unsigned*>(&p2);
                pk.w = *reinterpret_cast<unsigned*>(&p3);
                *reinterpret_cast<uint4*>(&s_Ah[(n - n0) * 128 + li * 8]) = pk;
            }
        }
    }
    __syncthreads();

    // wmma epilogue: D(64x32) = A(64x128,fp16) @ Wo(128x32,fp16), fp32 acc
    {
        int mt = w & 3, nt = w >> 2;
        wmma::fragment<wmma::accumulator, 16, 16, 16, float> c;
        wmma::fill_fragment(c, 0.f);
#pragma unroll
        for (int kk = 0; kk < 8; kk++) {
            wmma::fragment<wmma::matrix_a, 16, 16, 16, __half, wmma::row_major> a;
            wmma::load_matrix_sync(a, s_Ah + (mt * 16) * 128 + kk * 16, 128);
            wmma::fragment<wmma::matrix_b, 16, 16, 16, __half, wmma::row_major> bf;
            wmma::load_matrix_sync(bf, g_Wo_h + (kk * 16) * 32 + nt * 16, 32);
            wmma::mma_sync(c, a, bf, c);
        }
        __syncthreads();
        wmma::store_matrix_sync(sD + (mt * 16) * 32 + nt * 16, c, 32,
                                wmma::mem_row_major);
    }
    __syncthreads();

    // gelu + coalesced store (512 float4)
#pragma unroll
    for (int i = 0; i < 2; i++) {
        int idx = i * 256 + t;
        int r = idx >> 3, c4 = idx & 7;
        int gn = n0 + r;
        if (gn < N_NODES) {
            float4 v = *reinterpret_cast<const float4*>(&sD[r * 32 + c4 * 4]);
            float4 bb = *reinterpret_cast<const float4*>(&sb[c4 * 4]);
            v.x += bb.x; v.y += bb.y; v.z += bb.z; v.w += bb.w;
            v.x = 0.5f * v.x * (1.f + erff(v.x * 0.70710678118f));
            v.y = 0.5f * v.y * (1.f + erff(v.y * 0.70710678118f));
            v.z = 0.5f * v.z * (1.f + erff(v.z * 0.70710678118f));
            v.w = 0.5f * v.w * (1.f + erff(v.w * 0.70710678118f));
            *reinterpret_cast<float4*>(&out[(size_t)gn * 32 + c4 * 4]) = v;
        }
    }
}

extern "C" void kernel_launch(void* const* d_in, const int* in_sizes, int n_in,
                              void* d_out, int out_size) {
    const float* NF = (const float*)d_in[0];   // node_features (N,128)
    const int*   EI = (const int*)  d_in[1];   // edge_index (E,2)
    const float* EF = (const float*)d_in[2];   // edge_features (E,32)
    const float* Wn = (const float*)d_in[3];   // W_node (128,128)
    const float* We = (const float*)d_in[4];   // W_edge (32,128)
    const float* AK = (const float*)d_in[5];   // attn_kernel (4,96)
    const float* Wo = (const float*)d_in[6];   // W_out (128,32)
    const float* bo = (const float*)d_in[7];   // b_out (32,)
    float* out = (float*)d_out;                // (N,32)

    k_fold<<<1, 256>>>(We, AK, Wo, Wn);
    k_hist<<<HIST_BLOCKS, 256>>>(EI);
    k_scan<<<SCAN_BLOCKS, 1024>>>();
    k_gemm<<<GEMM_TILES, 256>>>(NF, AK);         // profiled slot (index 3)
    k_permute<<<N_EDGES / 256, 256>>>(EI, EF);
    k_agg_out<<<AGG_BLOCKS, 256>>>(bo, out);
}

// round 15
// speedup vs baseline: 1.3025x; 1.0077x over previous
#include <cuda_runtime.h>
#include <cuda_fp16.h>
#include <mma.h>
#include <math.h>

using namespace nvcuda;

#define N_NODES 100000
#define N_EDGES 1600000
#define F_IN    128
#define F_E     32
#define DH      128   // D*H
#define NH      4     // heads
#define FULLM   0xffffffffu
#define SCAN_BLOCKS 98          // ceil(100000/1024)
#define HIST_BLOCKS 6250        // 6250*256 = 1.6M edges
#define GEMM_TILES  1563        // ceil(100000/64)
#define AGG_NPB     64          // nodes per block in agg_out
#define AGG_BLOCKS  1563        // ceil(100000/64)
#define SA_LD       72          // padded stride (halves) for 64-wide A K-slice
#define SB_LD       136         // padded stride (halves) for B tile (272B -> CF LDSM)
#define SC_LD       132         // padded stride (floats) for 128-wide C tile
#define EF_LD       36          // padded stride (floats) for EF tile in permute

// -------- scratch (static device globals; zero-initialized at load) --------
__device__ __half2 g_np_h[(size_t)N_NODES * 64];      // node_proj fp16, 25.6 MB
__device__ float g_ssrc[N_NODES * NH];
__device__ float g_v[NH * F_E];                       // W_edge @ a_edge (per head)
__device__ __half g_Wo_h[DH * 32];                    // W_out in fp16
__device__ __half g_Wn_h[F_IN * DH];                  // W_node in fp16 (32 KB)
__device__ int g_cnt[N_NODES];                        // zeroed by prev run's agg_out
__device__ int g_rowptr[N_NODES + 1];
__device__ int g_head[N_NODES];
__device__ unsigned long long g_state[SCAN_BLOCKS];   // zeroed by prev run's agg_out
__device__ float4 g_p4[N_EDGES];                      // attn numerators, dst-sorted
__device__ int    g_src[N_EDGES];                     // src ids, dst-sorted

static __device__ __forceinline__ unsigned sm32(const void* p) {
    return (unsigned)__cvta_generic_to_shared(p);
}

// ===== launch 0: folds (block 0) + dst histogram (blocks 1..HIST) =====
__global__ void __launch_bounds__(256) k_fold_hist(const float* __restrict__ We,
                                                   const float* __restrict__ AK,
                                                   const float* __restrict__ Wo,
                                                   const float* __restrict__ Wn,
                                                   const int* __restrict__ EI) {
    int t = threadIdx.x, b = blockIdx.x;
    if (b > 0) {
        int e = (b - 1) * 256 + t;
        int2 ei = reinterpret_cast<const int2*>(EI)[e];
        atomicAdd(&g_cnt[ei.y], 1);
        return;
    }
    if (t < 128) {
        int h = t >> 5, k = t & 31;
        float s = 0.f;
#pragma unroll
        for (int d = 0; d < 32; d++)
            s += We[k * DH + h * 32 + d] * AK[h * 96 + 64 + d];
        g_v[t] = s;
    }
#pragma unroll
    for (int i = 0; i < 16; i++) {
        int idx = i * 256 + t;
        g_Wo_h[idx] = __float2half_rn(Wo[idx]);
    }
#pragma unroll
    for (int i = 0; i < 32; i++) {              // 8192 half2
        int idx = i * 256 + t;
        float2 w2 = reinterpret_cast<const float2*>(Wn)[idx];
        reinterpret_cast<__half2*>(g_Wn_h)[idx] = __floats2half2_rn(w2.x, w2.y);
    }
}

// ===== launch 1: single-pass decoupled-lookback scan -> rowptr + head =====
__global__ void __launch_bounds__(1024) k_scan() {
    __shared__ int s[1024];
    __shared__ int sprefix;
    int t = threadIdx.x, b = blockIdx.x;
    int i = b * 1024 + t;
    int v = (i < N_NODES) ? g_cnt[i] : 0;
    s[t] = v;
    __syncthreads();
    for (int o = 1; o < 1024; o <<= 1) {
        int u = (t >= o) ? s[t - o] : 0;
        __syncthreads();
        s[t] += u;
        __syncthreads();
    }
    int excl = s[t] - v;
    int total = s[1023];

    if (t == 0) {
        unsigned long long st = ((b == 0 ? 2ull : 1ull) << 32) | (unsigned)total;
        atomicExch(&g_state[b], st);
        if (b == 0) sprefix = 0;
    }
    if (b > 0 && t < 32) {
        int lane = t;
        unsigned running = 0;
        int idx = b - 1;
        while (true) {
            int pi = idx - lane;
            unsigned long long sv_ = (pi >= 0) ? atomicAdd(&g_state[pi], 0ull)
                                               : (2ull << 32);
            int flag = (int)(sv_ >> 32);
            unsigned val = (unsigned)sv_;
            unsigned m2 = __ballot_sync(FULLM, flag == 2);
            unsigned m0 = __ballot_sync(FULLM, flag == 0);
            int f2 = m2 ? (__ffs(m2) - 1) : 32;
            int f0 = m0 ? (__ffs(m0) - 1) : 32;
            if (f2 < f0) {
                unsigned cc = (lane <= f2) ? val : 0;
#pragma unroll
                for (int o = 16; o >= 1; o >>= 1) cc += __shfl_down_sync(FULLM, cc, o);
                if (lane == 0) running += cc;
                break;
            } else if (f0 < 32) {
                unsigned cc = (lane < f0) ? val : 0;
#pragma unroll
                for (int o = 16; o >= 1; o >>= 1) cc += __shfl_down_sync(FULLM, cc, o);
                if (lane == 0) running += cc;
                idx -= f0;
            } else {
                unsigned cc = val;
#pragma unroll
                for (int o = 16; o >= 1; o >>= 1) cc += __shfl_down_sync(FULLM, cc, o);
                if (lane == 0) running += cc;
                idx -= 32;
            }
        }
        if (lane == 0) {
            atomicExch(&g_state[b], (2ull << 32) | (unsigned)(running + total));
            sprefix = (int)running;
        }
    }
    __syncthreads();
    int P = sprefix;
    if (i < N_NODES) {
        int r = excl + P;
        g_rowptr[i] = r;
        g_head[i] = r;
    }
    if (b == 0 && t == 0) g_rowptr[N_NODES] = N_EDGES;
}

// ===== launch 2: node GEMM — padded smem B (CF LDSM) =====
__global__ void __launch_bounds__(256) k_gemm(const float* __restrict__ NF,
                                              const float* __restrict__ AK) {
    __shared__ __align__(16) __half sB[128 * SB_LD];  // 34816 B (aliased by sC)
    __shared__ __align__(16) __half sA[64 * SA_LD];   // 9216 B
    float* sC = reinterpret_cast<float*>(sB);         // 64 x SC_LD f32 (33792 B)
    int t = threadIdx.x;
    int row0 = blockIdx.x * 64;
    int w = t >> 5, wm = w >> 1, wn = w & 1;

    // stage B once: 128x128 halves from L1-resident g_Wn_h, padded rows
#pragma unroll
    for (int i = 0; i < 8; i++) {
        int idx = i * 256 + t;                 // uint4 index (2048 total)
        int r = idx >> 4, c8 = idx & 15;
        uint4 v = reinterpret_cast<const uint4*>(g_Wn_h)[idx];
        *reinterpret_cast<uint4*>(&sB[r * SB_LD + c8 * 8]) = v;
    }

    wmma::fragment<wmma::accumulator, 16, 16, 16, float> c[4];
#pragma unroll
    for (int j = 0; j < 4; j++) wmma::fill_fragment(c[j], 0.f);

#pragma unroll
    for (int kh = 0; kh < 2; kh++) {
        if (kh) __syncthreads();          // protect sA reuse
#pragma unroll
        for (int i = 0; i < 4; i++) {
            int idx = i * 256 + t;
            int r = idx >> 4, c4 = idx & 15;
            int gr = row0 + r;
            float4 v = (gr < N_NODES)
                ? reinterpret_cast<const float4*>(NF)[(size_t)gr * 32 + kh * 16 + c4]
                : make_float4(0.f, 0.f, 0.f, 0.f);
            __half2 h01 = __floats2half2_rn(v.x, v.y);
            __half2 h23 = __floats2half2_rn(v.z, v.w);
            uint2 raw;
            raw.x = *reinterpret_cast<unsigned*>(&h01);
            raw.y = *reinterpret_cast<unsigned*>(&h23);
            *reinterpret_cast<uint2*>(&sA[r * SA_LD + c4 * 4]) = raw;
        }
        __syncthreads();
#pragma unroll
        for (int k = 0; k < 4; k++) {
            wmma::fragment<wmma::matrix_a, 16, 16, 16, __half, wmma::row_major> a;
            wmma::load_matrix_sync(a, sA + (wm * 16) * SA_LD + k * 16, SA_LD);
#pragma unroll
            for (int j = 0; j < 4; j++) {
                wmma::fragment<wmma::matrix_b, 16, 16, 16, __half, wmma::row_major> bf;
                wmma::load_matrix_sync(bf,
                    sB + ((kh * 4 + k) * 16) * SB_LD + wn * 64 + j * 16, SB_LD);
                wmma::mma_sync(c[j], a, bf, c[j]);
            }
        }
    }
    __syncthreads();   // all mma done before sC aliases sB

#pragma unroll
    for (int j = 0; j < 4; j++)
        wmma::store_matrix_sync(sC + (wm * 16) * SC_LD + wn * 64 + j * 16, c[j],
                                SC_LD, wmma::mem_row_major);
    __syncthreads();

    // epilogue A: node_proj fp16 (64 rows x 64 half2)
#pragma unroll
    for (int i = 0; i < 16; i++) {
        int idx = i * 256 + t;
        int r = idx >> 6, c2 = idx & 63;
        int gr = row0 + r;
        if (gr < N_NODES) {
            float2 v = *reinterpret_cast<const float2*>(&sC[r * SC_LD + c2 * 2]);
            g_np_h[(size_t)gr * 64 + c2] = __floats2half2_rn(v.x, v.y);
        }
    }
    // epilogue B: ssrc (all 256 threads: r = t>>2, h = t&3)
    {
        int r = t >> 2, h = t & 3;
        int gr = row0 + r;
        if (gr < N_NODES) {
            const float4* akp = reinterpret_cast<const float4*>(AK + h * 96);
            const float* cr = sC + r * SC_LD + h * 32;
            float s = 0.f;
#pragma unroll
            for (int k4 = 0; k4 < 8; k4++) {
                float4 a = *reinterpret_cast<const float4*>(&cr[k4 * 4]);
                float4 ak = akp[k4];
                s += a.x * ak.x + a.y * ak.y + a.z * ak.z + a.w * ak.w;
            }
            g_ssrc[gr * 4 + h] = s;
        }
    }
}

// ===== launch 3 (PROFILED): permute — cp.async EF staging + tf32 wmma =====
// 256 edges/block: s_edge(256x4) = EF(256x32, tf32) @ V(32x16, 4 cols used)
__global__ void __launch_bounds__(256) k_permute(const int* __restrict__ EI,
                                                 const float* __restrict__ EF) {
    __shared__ __align__(16) float sEF[256 * EF_LD];  // 36864 B (aliased by sC)
    __shared__ __align__(16) float sV[32 * 20];       // 2560 B
    float* sC = sEF;                                  // 256 x 20 f32 (20480 B)
    int t = threadIdx.x, w = t >> 5;
    int e0 = blockIdx.x * 256;

    // early: edge endpoints + random ssrc gather (in flight during staging)
    int2 ei = reinterpret_cast<const int2*>(EI)[e0 + t];
    float4 ss4 = *reinterpret_cast<const float4*>(&g_ssrc[ei.x * 4]);

    // build V: B[k][n] = v_n[k] for n<4 else 0 (ldm 20)
    for (int i = t; i < 32 * 20; i += 256) {
        int k = i / 20, cn = i % 20;
        sV[i] = (cn < 4) ? g_v[cn * 32 + k] : 0.f;
    }
    // cp.async EF rows (raw fp32, 8 x 16B per thread), padded stride
#pragma unroll
    for (int i = 0; i < 8; i++) {
        int idx = i * 256 + t;
        int el = idx >> 3, c4 = idx & 7;
        unsigned dst = sm32(&sEF[el * EF_LD + c4 * 4]);
        const float* src = EF + (size_t)(e0 + el) * F_E + c4 * 4;
        asm volatile("cp.async.ca.shared.global [%0], [%1], 16;"
                     :: "r"(dst), "l"(src));
    }
    asm volatile("cp.async.commit_group;" ::: "memory");
    asm volatile("cp.async.wait_group 0;" ::: "memory");
    __syncthreads();

    // tf32 wmma: warp w does M-tiles 2w, 2w+1; K = 4 steps of 8
    wmma::fragment<wmma::accumulator, 16, 16, 8, float> cf[2];
#pragma unroll
    for (int mi = 0; mi < 2; mi++) {
        int mt = 2 * w + mi;
        wmma::fill_fragment(cf[mi], 0.f);
#pragma unroll
        for (int kk = 0; kk < 4; kk++) {
            wmma::fragment<wmma::matrix_a, 16, 16, 8, wmma::precision::tf32,
                           wmma::row_major> a;
            wmma::load_matrix_sync(a, sEF + (mt * 16) * EF_LD + kk * 8, EF_LD);
#pragma unroll
            for (int q = 0; q < a.num_elements; q++)
                a.x[q] = wmma::__float_to_tf32(a.x[q]);
            wmma::fragment<wmma::matrix_b, 16, 16, 8, wmma::precision::tf32,
                           wmma::row_major> bf;
            wmma::load_matrix_sync(bf, sV + (kk * 8) * 20, 20);
#pragma unroll
            for (int q = 0; q < bf.num_elements; q++)
                bf.x[q] = wmma::__float_to_tf32(bf.x[q]);
            wmma::mma_sync(cf[mi], a, bf, cf[mi]);
        }
    }
    __syncthreads();   // A fully consumed before aliasing writes
#pragma unroll
    for (int mi = 0; mi < 2; mi++)
        wmma::store_matrix_sync(sC + (2 * w + mi) * 16 * 20, cf[mi], 20,
                                wmma::mem_row_major);
    __syncthreads();

    float4 se = *reinterpret_cast<const float4*>(&sC[t * 20]);
    float4 p;
    p.x = __expf(ss4.x + se.x);
    p.y = __expf(ss4.y + se.y);
    p.z = __expf(ss4.z + se.z);
    p.w = __expf(ss4.w + se.w);
    int pos = atomicAdd(&g_head[ei.y], 1);
    g_p4[pos] = p;
    g_src[pos] = ei.x;
}

// ===== launch 4: gather-aggregate (4-deep pipeline) + wmma out-GEMM + gelu =
// block = 64 nodes; warp = 8 contiguous nodes; edges 16-lane rows (pairs).
__global__ void __launch_bounds__(256) k_agg_out(const float* __restrict__ bo,
                                                 float* __restrict__ out) {
    __shared__ __align__(16) unsigned char sm[36992];
    float*  s_p   = reinterpret_cast<float*>(sm);            // [4][8][32*4] 16 KB
    int*    s_srb = reinterpret_cast<int*>(sm + 16384);      // [4][8][32]   4 KB
    __half* s_Ah  = reinterpret_cast<__half*>(sm + 20480);   // [64][128]   16 KB
    float*  sD    = reinterpret_cast<float*>(sm);            // alias (epilogue)
    float*  sb    = reinterpret_cast<float*>(sm + 36864);    // 32 floats
    int t = threadIdx.x, lane = t & 31, w = t >> 5;

    // re-zero hist/scan state for the NEXT run
    {
        int zi = blockIdx.x * 256 + t;
        if (zi < N_NODES) g_cnt[zi] = 0;
        if (blockIdx.x == 0 && t < SCAN_BLOCKS) g_state[t] = 0ull;
    }
    if (t < 32) sb[t] = bo[t];

    int n0 = blockIdx.x * AGG_NPB;
    int nw0 = n0 + w * 8;
    int nw1 = min(nw0 + 8, N_NODES);

    if (nw0 < N_NODES) {
        int ebeg = g_rowptr[nw0];
        int eend = g_rowptr[nw1];
        int half = lane >> 4, li = lane & 15, h = li >> 2;
        const uint4* np4 = reinterpret_cast<const uint4*>(g_np_h);

        auto issue = [&](int cs) {
            int buf = ((cs - ebeg) >> 5) & 3;
            int j = cs + lane;
            if (j < eend) {
                unsigned ap = sm32(s_p + (buf * 8 + w) * 128 + lane * 4);
                asm volatile("cp.async.ca.shared.global [%0], [%1], 16;"
                             :: "r"(ap), "l"(g_p4 + j));
                unsigned as = sm32(s_srb + (buf * 8 + w) * 32 + lane);
                asm volatile("cp.async.ca.shared.global [%0], [%1], 4;"
                             :: "r"(as), "l"(g_src + j));
            }
            asm volatile("cp.async.commit_group;" ::: "memory");
        };

        if (ebeg < eend) {
            issue(ebeg);
            if (ebeg + 32 < eend) issue(ebeg + 32);
            if (ebeg + 64 < eend) issue(ebeg + 64);
        }

        int j = ebeg;
        for (int n = nw0; n < nw1; n++) {
            int en = g_rowptr[n + 1];
            float acc[8] = {0.f, 0.f, 0.f, 0.f, 0.f, 0.f, 0.f, 0.f};
            float ds = 0.f;

            while (j < en) {
                int cb = ebeg + ((j - ebeg) & ~31);
                int ce = min(cb + 32, eend);
                if (j == cb) {                    // entering chunk: wait for it
                    if (cb + 64 < eend) {
                        asm volatile("cp.async.wait_group 2;" ::: "memory");
                    } else if (cb + 32 < eend) {
                        asm volatile("cp.async.wait_group 1;" ::: "memory");
                    } else {
                        asm volatile("cp.async.wait_group 0;" ::: "memory");
                    }
                    __syncwarp();
                }
                int buf = ((cb - ebeg) >> 5) & 3;
                const float* wp = s_p + (buf * 8 + w) * 128;
                const int* ws = s_srb + (buf * 8 + w) * 32;
                int stop = min(en, ce);
                int npair = (stop - j + 1) >> 1;
#pragma unroll 4
                for (int qp = 0; qp < npair; qp++) {
                    int e = j + qp * 2 + half;
                    bool valid = e < stop;
                    int qq = (e - ebeg) & 31;
                    int src = valid ? ws[qq] : 0;
                    float ph = valid ? wp[qq * 4 + h] : 0.f;
                    uint4 raw = np4[(size_t)src * 16 + li];
                    float2 f0 = __half22float2(*reinterpret_cast<__half2*>(&raw.x));
                    float2 f1 = __half22float2(*reinterpret_cast<__half2*>(&raw.y));
                    float2 f2 = __half22float2(*reinterpret_cast<__half2*>(&raw.z));
                    float2 f3 = __half22float2(*reinterpret_cast<__half2*>(&raw.w));
                    acc[0] += ph * f0.x; acc[1] += ph * f0.y;
                    acc[2] += ph * f1.x; acc[3] += ph * f1.y;
                    acc[4] += ph * f2.x; acc[5] += ph * f2.y;
                    acc[6] += ph * f3.x; acc[7] += ph * f3.y;
                    ds += ph;
                }
                j = stop;
                if (stop == ce) {                 // finished chunk: refill +3
                    __syncwarp();
                    if (cb + 96 < eend) issue(cb + 96);
                }
            }

#pragma unroll
            for (int k = 0; k < 8; k++)
                acc[k] += __shfl_xor_sync(FULLM, acc[k], 16);
            ds += __shfl_xor_sync(FULLM, ds, 16);
            float inv = 1.f / (ds + 1e-8f);
            if (half == 0) {
                __half2 p0 = __floats2half2_rn(acc[0] * inv, acc[1] * inv);
                __half2 p1 = __floats2half2_rn(acc[2] * inv, acc[3] * inv);
                __half2 p2 = __floats2half2_rn(acc[4] * inv, acc[5] * inv);
                __half2 p3 = __floats2half2_rn(acc[6] * inv, acc[7] * inv);
                uint4 pk;
                pk.x = *reinterpret_cast<unsigned*>(&p0);
                pk.y = *reinterpret_cast<unsigned*>(&p1);
                pk.z = *reinterpret_cast<unsigned*>(&p2);
                pk.w = *reinterpret_cast<unsigned*>(&p3);
                *reinterpret_cast<uint4*>(&s_Ah[(n - n0) * 128 + li * 8]) = pk;
            }
        }
    }
    __syncthreads();

    // wmma epilogue: D(64x32) = A(64x128,fp16) @ Wo(128x32,fp16), fp32 acc
    {
        int mt = w & 3, nt = w >> 2;
        wmma::fragment<wmma::accumulator, 16, 16, 16, float> c;
        wmma::fill_fragment(c, 0.f);
#pragma unroll
        for (int kk = 0; kk < 8; kk++) {
            wmma::fragment<wmma::matrix_a, 16, 16, 16, __half, wmma::row_major> a;
            wmma::load_matrix_sync(a, s_Ah + (mt * 16) * 128 + kk * 16, 128);
            wmma::fragment<wmma::matrix_b, 16, 16, 16, __half, wmma::row_major> bf;
            wmma::load_matrix_sync(bf, g_Wo_h + (kk * 16) * 32 + nt * 16, 32);
            wmma::mma_sync(c, a, bf, c);
        }
        __syncthreads();   // s_p readers done before aliasing writes
        wmma::store_matrix_sync(sD + (mt * 16) * 32 + nt * 16, c, 32,
                                wmma::mem_row_major);
    }
    __syncthreads();

    // gelu + coalesced store (512 float4)
#pragma unroll
    for (int i = 0; i < 2; i++) {
        int idx = i * 256 + t;
        int r = idx >> 3, c4 = idx & 7;
        int gn = n0 + r;
        if (gn < N_NODES) {
            float4 v = *reinterpret_cast<const float4*>(&sD[r * 32 + c4 * 4]);
            float4 bb = *reinterpret_cast<const float4*>(&sb[c4 * 4]);
            v.x += bb.x; v.y += bb.y; v.z += bb.z; v.w += bb.w;
            v.x = 0.5f * v.x * (1.f + erff(v.x * 0.70710678118f));
            v.y = 0.5f * v.y * (1.f + erff(v.y * 0.70710678118f));
            v.z = 0.5f * v.z * (1.f + erff(v.z * 0.70710678118f));
            v.w = 0.5f * v.w * (1.f + erff(v.w * 0.70710678118f));
            *reinterpret_cast<float4*>(&out[(size_t)gn * 32 + c4 * 4]) = v;
        }
    }
}

extern "C" void kernel_launch(void* const* d_in, const int* in_sizes, int n_in,
                              void* d_out, int out_size) {
    const float* NF = (const float*)d_in[0];   // node_features (N,128)
    const int*   EI = (const int*)  d_in[1];   // edge_index (E,2)
    const float* EF = (const float*)d_in[2];   // edge_features (E,32)
    const float* Wn = (const float*)d_in[3];   // W_node (128,128)
    const float* We = (const float*)d_in[4];   // W_edge (32,128)
    const float* AK = (const float*)d_in[5];   // attn_kernel (4,96)
    const float* Wo = (const float*)d_in[6];   // W_out (128,32)
    const float* bo = (const float*)d_in[7];   // b_out (32,)
    float* out = (float*)d_out;                // (N,32)

    k_fold_hist<<<HIST_BLOCKS + 1, 256>>>(We, AK, Wo, Wn, EI);
    k_scan<<<SCAN_BLOCKS, 1024>>>();
    k_gemm<<<GEMM_TILES, 256>>>(NF, AK);
    k_permute<<<N_EDGES / 256, 256>>>(EI, EF);   // profiled slot (index 3)
    k_agg_out<<<AGG_BLOCKS, 256>>>(bo, out);
}

// round 16
// speedup vs baseline: 1.3575x; 1.0422x over previous
#include <cuda_runtime.h>
#include <cuda_fp16.h>
#include <mma.h>
#include <math.h>

using namespace nvcuda;

#define N_NODES 100000
#define N_EDGES 1600000
#define F_IN    128
#define F_E     32
#define DH      128   // D*H
#define NH      4     // heads
#define FULLM   0xffffffffu
#define HIST_BLOCKS 6250        // 6250*256 = 1.6M edges
#define SCAN2_BLOCKS 391        // ceil(100000/256)
#define GEMM_TILES  1563        // ceil(100000/64)
#define AGG_NPB     64          // nodes per block in agg_out
#define AGG_BLOCKS  1563        // ceil(100000/64)
#define SA_LD       72          // padded stride (halves) for 64-wide A K-slice
#define SB_LD       136         // padded stride (halves) for B tile (272B -> CF LDSM)
#define SC_LD       132         // padded stride (floats) for 128-wide C tile

// -------- scratch (static device globals; zero-initialized at load) --------
__device__ __half2 g_np_h[(size_t)N_NODES * 64];      // node_proj fp16, 25.6 MB
__device__ float g_ssrc[N_NODES * NH];
__device__ float g_v[NH * F_E];                       // W_edge @ a_edge (per head)
__device__ __half g_Wo_h[DH * 32];                    // W_out in fp16
__device__ __half g_Wn_h[F_IN * DH];                  // W_node in fp16 (32 KB)
__device__ int g_cnt[N_NODES];                        // zeroed by prev run's agg_out
__device__ int g_rowptr[N_NODES + 1];
__device__ int g_head[N_NODES];
__device__ unsigned long long g_state[512];           // zeroed by prev run's agg_out
__device__ float4 g_p4[N_EDGES];                      // attn numerators, dst-sorted
__device__ int    g_src[N_EDGES];                     // src ids, dst-sorted

static __device__ __forceinline__ unsigned sm32(const void* p) {
    return (unsigned)__cvta_generic_to_shared(p);
}

// ===== launch 0: folds (block 0) + dst histogram (blocks 1..HIST) =====
__global__ void __launch_bounds__(256) k_fold_hist(const float* __restrict__ We,
                                                   const float* __restrict__ AK,
                                                   const float* __restrict__ Wo,
                                                   const float* __restrict__ Wn,
                                                   const int* __restrict__ EI) {
    int t = threadIdx.x, b = blockIdx.x;
    if (b > 0) {
        int e = (b - 1) * 256 + t;
        int2 ei = reinterpret_cast<const int2*>(EI)[e];
        atomicAdd(&g_cnt[ei.y], 1);
        return;
    }
    if (t < 128) {
        int h = t >> 5, k = t & 31;
        float s = 0.f;
#pragma unroll
        for (int d = 0; d < 32; d++)
            s += We[k * DH + h * 32 + d] * AK[h * 96 + 64 + d];
        g_v[t] = s;
    }
#pragma unroll
    for (int i = 0; i < 16; i++) {
        int idx = i * 256 + t;
        g_Wo_h[idx] = __float2half_rn(Wo[idx]);
    }
#pragma unroll
    for (int i = 0; i < 32; i++) {              // 8192 half2
        int idx = i * 256 + t;
        float2 w2 = reinterpret_cast<const float2*>(Wn)[idx];
        reinterpret_cast<__half2*>(g_Wn_h)[idx] = __floats2half2_rn(w2.x, w2.y);
    }
}

// ===== launch 1: scan (blocks 0..390) + node GEMM (blocks 391..) =====
__global__ void __launch_bounds__(256) k_scan_gemm(const float* __restrict__ NF,
                                                   const float* __restrict__ AK) {
    __shared__ __align__(16) __half sB[128 * SB_LD];  // 34816 B (aliased by sC)
    __shared__ __align__(16) __half sA[64 * SA_LD];   // 9216 B
    __shared__ int ss[256];
    __shared__ int sprefix;
    float* sC = reinterpret_cast<float*>(sB);         // 64 x SC_LD f32
    int t = threadIdx.x, b = blockIdx.x;

    if (b < SCAN2_BLOCKS) {
        // ---- decoupled-lookback scan (256-thread blocks) ----
        int i = b * 256 + t;
        int v = (i < N_NODES) ? g_cnt[i] : 0;
        ss[t] = v;
        __syncthreads();
        for (int o = 1; o < 256; o <<= 1) {
            int u = (t >= o) ? ss[t - o] : 0;
            __syncthreads();
            ss[t] += u;
            __syncthreads();
        }
        int excl = ss[t] - v;
        int total = ss[255];

        if (t == 0) {
            unsigned long long st = ((b == 0 ? 2ull : 1ull) << 32) | (unsigned)total;
            atomicExch(&g_state[b], st);
            if (b == 0) sprefix = 0;
        }
        if (b > 0 && t < 32) {
            int lane = t;
            unsigned running = 0;
            int idx = b - 1;
            while (true) {
                int pi = idx - lane;
                unsigned long long sv_ = (pi >= 0) ? atomicAdd(&g_state[pi], 0ull)
                                                   : (2ull << 32);
                int flag = (int)(sv_ >> 32);
                unsigned val = (unsigned)sv_;
                unsigned m2 = __ballot_sync(FULLM, flag == 2);
                unsigned m0 = __ballot_sync(FULLM, flag == 0);
                int f2 = m2 ? (__ffs(m2) - 1) : 32;
                int f0 = m0 ? (__ffs(m0) - 1) : 32;
                if (f2 < f0) {
                    unsigned cc = (lane <= f2) ? val : 0;
#pragma unroll
                    for (int o = 16; o >= 1; o >>= 1) cc += __shfl_down_sync(FULLM, cc, o);
                    if (lane == 0) running += cc;
                    break;
                } else if (f0 < 32) {
                    unsigned cc = (lane < f0) ? val : 0;
#pragma unroll
                    for (int o = 16; o >= 1; o >>= 1) cc += __shfl_down_sync(FULLM, cc, o);
                    if (lane == 0) running += cc;
                    idx -= f0;
                } else {
                    unsigned cc = val;
#pragma unroll
                    for (int o = 16; o >= 1; o >>= 1) cc += __shfl_down_sync(FULLM, cc, o);
                    if (lane == 0) running += cc;
                    idx -= 32;
                }
            }
            if (lane == 0) {
                atomicExch(&g_state[b], (2ull << 32) | (unsigned)(running + total));
                sprefix = (int)running;
            }
        }
        __syncthreads();
        int P = sprefix;
        if (i < N_NODES) {
            int r = excl + P;
            g_rowptr[i] = r;
            g_head[i] = r;
        }
        if (b == 0 && t == 0) g_rowptr[N_NODES] = N_EDGES;
        return;
    }

    // ---- node GEMM tile ----
    int row0 = (b - SCAN2_BLOCKS) * 64;
    int w = t >> 5, wm = w >> 1, wn = w & 1;

    // stage B once: 128x128 halves from L1-resident g_Wn_h, padded rows
#pragma unroll
    for (int i = 0; i < 8; i++) {
        int idx = i * 256 + t;                 // uint4 index (2048 total)
        int r = idx >> 4, c8 = idx & 15;
        uint4 v = reinterpret_cast<const uint4*>(g_Wn_h)[idx];
        *reinterpret_cast<uint4*>(&sB[r * SB_LD + c8 * 8]) = v;
    }

    wmma::fragment<wmma::accumulator, 16, 16, 16, float> c[4];
#pragma unroll
    for (int j = 0; j < 4; j++) wmma::fill_fragment(c[j], 0.f);

#pragma unroll
    for (int kh = 0; kh < 2; kh++) {
        if (kh) __syncthreads();          // protect sA reuse
#pragma unroll
        for (int i = 0; i < 4; i++) {
            int idx = i * 256 + t;
            int r = idx >> 4, c4 = idx & 15;
            int gr = row0 + r;
            float4 v = (gr < N_NODES)
                ? reinterpret_cast<const float4*>(NF)[(size_t)gr * 32 + kh * 16 + c4]
                : make_float4(0.f, 0.f, 0.f, 0.f);
            __half2 h01 = __floats2half2_rn(v.x, v.y);
            __half2 h23 = __floats2half2_rn(v.z, v.w);
            uint2 raw;
            raw.x = *reinterpret_cast<unsigned*>(&h01);
            raw.y = *reinterpret_cast<unsigned*>(&h23);
            *reinterpret_cast<uint2*>(&sA[r * SA_LD + c4 * 4]) = raw;
        }
        __syncthreads();
#pragma unroll
        for (int k = 0; k < 4; k++) {
            wmma::fragment<wmma::matrix_a, 16, 16, 16, __half, wmma::row_major> a;
            wmma::load_matrix_sync(a, sA + (wm * 16) * SA_LD + k * 16, SA_LD);
#pragma unroll
            for (int j = 0; j < 4; j++) {
                wmma::fragment<wmma::matrix_b, 16, 16, 16, __half, wmma::row_major> bf;
                wmma::load_matrix_sync(bf,
                    sB + ((kh * 4 + k) * 16) * SB_LD + wn * 64 + j * 16, SB_LD);
                wmma::mma_sync(c[j], a, bf, c[j]);
            }
        }
    }
    __syncthreads();   // all mma done before sC aliases sB

#pragma unroll
    for (int j = 0; j < 4; j++)
        wmma::store_matrix_sync(sC + (wm * 16) * SC_LD + wn * 64 + j * 16, c[j],
                                SC_LD, wmma::mem_row_major);
    __syncthreads();

    // epilogue A: node_proj fp16 (64 rows x 64 half2)
#pragma unroll
    for (int i = 0; i < 16; i++) {
        int idx = i * 256 + t;
        int r = idx >> 6, c2 = idx & 63;
        int gr = row0 + r;
        if (gr < N_NODES) {
            float2 v = *reinterpret_cast<const float2*>(&sC[r * SC_LD + c2 * 2]);
            g_np_h[(size_t)gr * 64 + c2] = __floats2half2_rn(v.x, v.y);
        }
    }
    // epilogue B: ssrc (all 256 threads: r = t>>2, h = t&3)
    {
        int r = t >> 2, h = t & 3;
        int gr = row0 + r;
        if (gr < N_NODES) {
            const float4* akp = reinterpret_cast<const float4*>(AK + h * 96);
            const float* cr = sC + r * SC_LD + h * 32;
            float s = 0.f;
#pragma unroll
            for (int k4 = 0; k4 < 8; k4++) {
                float4 a = *reinterpret_cast<const float4*>(&cr[k4 * 4]);
                float4 ak = akp[k4];
                s += a.x * ak.x + a.y * ak.y + a.z * ak.z + a.w * ak.w;
            }
            g_ssrc[gr * 4 + h] = s;
        }
    }
}

// ===== launch 2: permute via fp16 wmma edge-score GEMM =====
// 256 edges/block: s_edge(256x4) = EF_h(256x32) @ V(32x16, 4 cols used)
__global__ void __launch_bounds__(256) k_permute(const int* __restrict__ EI,
                                                 const float* __restrict__ EF) {
    __shared__ __align__(16) unsigned char psm[21504];
    __half* sEFh = reinterpret_cast<__half*>(psm);        // 256x32 fp16 (16 KB)
    float*  sC   = reinterpret_cast<float*>(psm);         // 256x20 f32 (alias)
    __half* sV   = reinterpret_cast<__half*>(psm + 20480);// 32x16 fp16 (1 KB)
    int t = threadIdx.x, w = t >> 5;
    int e0 = blockIdx.x * 256;

    // early: edge endpoints + random ssrc gather (in flight during staging)
    int2 ei = reinterpret_cast<const int2*>(EI)[e0 + t];
    float4 ss4 = *reinterpret_cast<const float4*>(&g_ssrc[ei.x * 4]);

#pragma unroll
    for (int i = 0; i < 2; i++) {
        int idx = i * 256 + t;
        int k = idx >> 4, cn = idx & 15;
        sV[idx] = (cn < 4) ? __float2half_rn(g_v[cn * 32 + k]) : __ushort_as_half(0);
    }
#pragma unroll
    for (int i = 0; i < 8; i++) {
        int idx = i * 256 + t;
        int el = idx >> 3, c4 = idx & 7;
        float4 v = reinterpret_cast<const float4*>(EF)[(size_t)(e0 + el) * 8 + c4];
        __half2 ha = __floats2half2_rn(v.x, v.y);
        __half2 hb = __floats2half2_rn(v.z, v.w);
        uint2 raw;
        raw.x = *reinterpret_cast<unsigned*>(&ha);
        raw.y = *reinterpret_cast<unsigned*>(&hb);
        *reinterpret_cast<uint2*>(&sEFh[el * 32 + c4 * 4]) = raw;
    }
    __syncthreads();

    wmma::fragment<wmma::accumulator, 16, 16, 16, float> cf[2];
#pragma unroll
    for (int mi = 0; mi < 2; mi++) {
        int mt = 2 * w + mi;
        wmma::fill_fragment(cf[mi], 0.f);
#pragma unroll
        for (int kk = 0; kk < 2; kk++) {
            wmma::fragment<wmma::matrix_a, 16, 16, 16, __half, wmma::row_major> a;
            wmma::load_matrix_sync(a, sEFh + (mt * 16) * 32 + kk * 16, 32);
            wmma::fragment<wmma::matrix_b, 16, 16, 16, __half, wmma::row_major> bf;
            wmma::load_matrix_sync(bf, sV + (kk * 16) * 16, 16);
            wmma::mma_sync(cf[mi], a, bf, cf[mi]);
        }
    }
    __syncthreads();   // A fully consumed before aliasing writes
#pragma unroll
    for (int mi = 0; mi < 2; mi++)
        wmma::store_matrix_sync(sC + (2 * w + mi) * 16 * 20, cf[mi], 20,
                                wmma::mem_row_major);
    __syncthreads();

    float4 se = *reinterpret_cast<const float4*>(&sC[t * 20]);
    float4 p;
    p.x = __expf(ss4.x + se.x);
    p.y = __expf(ss4.y + se.y);
    p.z = __expf(ss4.z + se.z);
    p.w = __expf(ss4.w + se.w);
    int pos = atomicAdd(&g_head[ei.y], 1);
    g_p4[pos] = p;
    g_src[pos] = ei.x;
}

// ===== launch 3 (PROFILED): gather-aggregate (4-deep) + wmma out + gelu ===
// block = 64 nodes; warp = 8 contiguous nodes; edges 16-lane rows (pairs).
__global__ void __launch_bounds__(256) k_agg_out(const float* __restrict__ bo,
                                                 float* __restrict__ out) {
    __shared__ __align__(16) unsigned char sm[36992];
    float*  s_p   = reinterpret_cast<float*>(sm);            // [4][8][32*4] 16 KB
    int*    s_srb = reinterpret_cast<int*>(sm + 16384);      // [4][8][32]   4 KB
    __half* s_Ah  = reinterpret_cast<__half*>(sm + 20480);   // [64][128]   16 KB
    float*  sD    = reinterpret_cast<float*>(sm);            // alias (epilogue)
    float*  sb    = reinterpret_cast<float*>(sm + 36864);    // 32 floats
    int t = threadIdx.x, lane = t & 31, w = t >> 5;

    // re-zero hist/scan state for the NEXT run
    {
        int zi = blockIdx.x * 256 + t;
        if (zi < N_NODES) g_cnt[zi] = 0;
        if (blockIdx.x == 0) {
            for (int q = t; q < 512; q += 256) g_state[q] = 0ull;
        }
    }
    if (t < 32) sb[t] = bo[t];

    int n0 = blockIdx.x * AGG_NPB;
    int nw0 = n0 + w * 8;
    int nw1 = min(nw0 + 8, N_NODES);

    if (nw0 < N_NODES) {
        int ebeg = g_rowptr[nw0];
        int eend = g_rowptr[nw1];
        int half = lane >> 4, li = lane & 15, h = li >> 2;
        const uint4* np4 = reinterpret_cast<const uint4*>(g_np_h);

        auto issue = [&](int cs) {
            int buf = ((cs - ebeg) >> 5) & 3;
            int j = cs + lane;
            if (j < eend) {
                unsigned ap = sm32(s_p + (buf * 8 + w) * 128 + lane * 4);
                asm volatile("cp.async.ca.shared.global [%0], [%1], 16;"
                             :: "r"(ap), "l"(g_p4 + j));
                unsigned as = sm32(s_srb + (buf * 8 + w) * 32 + lane);
                asm volatile("cp.async.ca.shared.global [%0], [%1], 4;"
                             :: "r"(as), "l"(g_src + j));
            }
            asm volatile("cp.async.commit_group;" ::: "memory");
        };

        if (ebeg < eend) {
            issue(ebeg);
            if (ebeg + 32 < eend) issue(ebeg + 32);
            if (ebeg + 64 < eend) issue(ebeg + 64);
        }

        int j = ebeg;
        for (int n = nw0; n < nw1; n++) {
            int en = g_rowptr[n + 1];
            float acc[8] = {0.f, 0.f, 0.f, 0.f, 0.f, 0.f, 0.f, 0.f};
            float ds = 0.f;

            while (j < en) {
                int cb = ebeg + ((j - ebeg) & ~31);
                int ce = min(cb + 32, eend);
                if (j == cb) {                    // entering chunk: wait for it
                    if (cb + 64 < eend) {
                        asm volatile("cp.async.wait_group 2;" ::: "memory");
                    } else if (cb + 32 < eend) {
                        asm volatile("cp.async.wait_group 1;" ::: "memory");
                    } else {
                        asm volatile("cp.async.wait_group 0;" ::: "memory");
                    }
                    __syncwarp();
                }
                int buf = ((cb - ebeg) >> 5) & 3;
                const float* wp = s_p + (buf * 8 + w) * 128;
                const int* ws = s_srb + (buf * 8 + w) * 32;
                int stop = min(en, ce);
                int npair = (stop - j + 1) >> 1;
#pragma unroll 4
                for (int qp = 0; qp < npair; qp++) {
                    int e = j + qp * 2 + half;
                    bool valid = e < stop;
                    int qq = (e - ebeg) & 31;
                    int src = valid ? ws[qq] : 0;
                    float ph = valid ? wp[qq * 4 + h] : 0.f;
                    uint4 raw = np4[(size_t)src * 16 + li];
                    float2 f0 = __half22float2(*reinterpret_cast<__half2*>(&raw.x));
                    float2 f1 = __half22float2(*reinterpret_cast<__half2*>(&raw.y));
                    float2 f2 = __half22float2(*reinterpret_cast<__half2*>(&raw.z));
                    float2 f3 = __half22float2(*reinterpret_cast<__half2*>(&raw.w));
                    acc[0] += ph * f0.x; acc[1] += ph * f0.y;
                    acc[2] += ph * f1.x; acc[3] += ph * f1.y;
                    acc[4] += ph * f2.x; acc[5] += ph * f2.y;
                    acc[6] += ph * f3.x; acc[7] += ph * f3.y;
                    ds += ph;
                }
                j = stop;
                if (stop == ce) {                 // finished chunk: refill +3
                    __syncwarp();
                    if (cb + 96 < eend) issue(cb + 96);
                }
            }

#pragma unroll
            for (int k = 0; k < 8; k++)
                acc[k] += __shfl_xor_sync(FULLM, acc[k], 16);
            ds += __shfl_xor_sync(FULLM, ds, 16);
            float inv = 1.f / (ds + 1e-8f);
            if (half == 0) {
                __half2 p0 = __floats2half2_rn(acc[0] * inv, acc[1] * inv);
                __half2 p1 = __floats2half2_rn(acc[2] * inv, acc[3] * inv);
                __half2 p2 = __floats2half2_rn(acc[4] * inv, acc[5] * inv);
                __half2 p3 = __floats2half2_rn(acc[6] * inv, acc[7] * inv);
                uint4 pk;
                pk.x = *reinterpret_cast<unsigned*>(&p0);
                pk.y = *reinterpret_cast<unsigned*>(&p1);
                pk.z = *reinterpret_cast<unsigned*>(&p2);
                pk.w = *reinterpret_cast<unsigned*>(&p3);
                *reinterpret_cast<uint4*>(&s_Ah[(n - n0) * 128 + li * 8]) = pk;
            }
        }
    }
    __syncthreads();

    // wmma epilogue: D(64x32) = A(64x128,fp16) @ Wo(128x32,fp16), fp32 acc
    {
        int mt = w & 3, nt = w >> 2;
        wmma::fragment<wmma::accumulator, 16, 16, 16, float> c;
        wmma::fill_fragment(c, 0.f);
#pragma unroll
        for (int kk = 0; kk < 8; kk++) {
            wmma::fragment<wmma::matrix_a, 16, 16, 16, __half, wmma::row_major> a;
            wmma::load_matrix_sync(a, s_Ah + (mt * 16) * 128 + kk * 16, 128);
            wmma::fragment<wmma::matrix_b, 16, 16, 16, __half, wmma::row_major> bf;
            wmma::load_matrix_sync(bf, g_Wo_h + (kk * 16) * 32 + nt * 16, 32);
            wmma::mma_sync(c, a, bf, c);
        }
        __syncthreads();   // s_p readers done before aliasing writes
        wmma::store_matrix_sync(sD + (mt * 16) * 32 + nt * 16, c, 32,
                                wmma::mem_row_major);
    }
    __syncthreads();

    // gelu + coalesced store (512 float4)
#pragma unroll
    for (int i = 0; i < 2; i++) {
        int idx = i * 256 + t;
        int r = idx >> 3, c4 = idx & 7;
        int gn = n0 + r;
        if (gn < N_NODES) {
            float4 v = *reinterpret_cast<const float4*>(&sD[r * 32 + c4 * 4]);
            float4 bb = *reinterpret_cast<const float4*>(&sb[c4 * 4]);
            v.x += bb.x; v.y += bb.y; v.z += bb.z; v.w += bb.w;
            v.x = 0.5f * v.x * (1.f + erff(v.x * 0.70710678118f));
            v.y = 0.5f * v.y * (1.f + erff(v.y * 0.70710678118f));
            v.z = 0.5f * v.z * (1.f + erff(v.z * 0.70710678118f));
            v.w = 0.5f * v.w * (1.f + erff(v.w * 0.70710678118f));
            *reinterpret_cast<float4*>(&out[(size_t)gn * 32 + c4 * 4]) = v;
        }
    }
}

extern "C" void kernel_launch(void* const* d_in, const int* in_sizes, int n_in,
                              void* d_out, int out_size) {
    const float* NF = (const float*)d_in[0];   // node_features (N,128)
    const int*   EI = (const int*)  d_in[1];   // edge_index (E,2)
    const float* EF = (const float*)d_in[2];   // edge_features (E,32)
    const float* Wn = (const float*)d_in[3];   // W_node (128,128)
    const float* We = (const float*)d_in[4];   // W_edge (32,128)
    const float* AK = (const float*)d_in[5];   // attn_kernel (4,96)
    const float* Wo = (const float*)d_in[6];   // W_out (128,32)
    const float* bo = (const float*)d_in[7];   // b_out (32,)
    float* out = (float*)d_out;                // (N,32)

    k_fold_hist<<<HIST_BLOCKS + 1, 256>>>(We, AK, Wo, Wn, EI);
    k_scan_gemm<<<SCAN2_BLOCKS + GEMM_TILES, 256>>>(NF, AK);
    k_permute<<<N_EDGES / 256, 256>>>(EI, EF);
    k_agg_out<<<AGG_BLOCKS, 256>>>(bo, out);     // profiled slot (index 3)
}